// round 5
// baseline (speedup 1.0000x reference)
#include <cuda_runtime.h>
#include <cuda_bf16.h>
#include <cstdint>
#include <math.h>

#define BATCH 8192
#define EDIM  256
#define HDIM  50
#define N_INNER 31
#define N_LEAF  32

// ---------------------------------------------------------------------------
// Device scratch
// ---------------------------------------------------------------------------
__device__ float g_pR[N_INNER * BATCH];
__device__ float g_yleaf[N_LEAF * BATCH];

__device__ __nv_bfloat16 g_xh[BATCH * EDIM];
__device__ __nv_bfloat16 g_xl[BATCH * EDIM];
__device__ __nv_bfloat16 g_e0h[BATCH * EDIM];
__device__ __nv_bfloat16 g_e0l[BATCH * EDIM];
__device__ __nv_bfloat16 g_e1h[BATCH * EDIM];
__device__ __nv_bfloat16 g_e1l[BATCH * EDIM];
// transposed weights: 0..3 encoder, 4..35 leaves. layout [mat][N=256][K=256]
__device__ __nv_bfloat16 g_wth[36 * 65536];
__device__ __nv_bfloat16 g_wtl[36 * 65536];
// inner: W1 transposed [31][64][256] (rows 50..63 zero)
__device__ __nv_bfloat16 g_w1th[N_INNER * 64 * 256];
__device__ __nv_bfloat16 g_w1tl[N_INNER * 64 * 256];
// inner: Ww transposed [31][256][64] (cols 50..63 zero)
__device__ __nv_bfloat16 g_wwth[N_INNER * 256 * 64];
__device__ __nv_bfloat16 g_wwtl[N_INNER * 256 * 64];

// ---------------------------------------------------------------------------
// Helpers
// ---------------------------------------------------------------------------
__device__ __forceinline__ uint32_t smem_u32(const void* p) {
    uint32_t a;
    asm("{ .reg .u64 t; cvta.to.shared.u64 t, %1; cvt.u32.u64 %0, t; }" : "=r"(a) : "l"(p));
    return a;
}
#define CP_ASYNC16(dst, src) \
    asm volatile("cp.async.cg.shared.global [%0], [%1], 16;" :: "r"(dst), "l"(src) : "memory")
#define CP_COMMIT() asm volatile("cp.async.commit_group;" ::: "memory")
#define CP_WAIT1()  asm volatile("cp.async.wait_group 1;" ::: "memory")
#define CP_WAIT0()  asm volatile("cp.async.wait_group 0;" ::: "memory")

#define LDSM4(r, addr) \
    asm volatile("ldmatrix.sync.aligned.m8n8.x4.shared.b16 {%0,%1,%2,%3}, [%4];" \
        : "=r"((r)[0]), "=r"((r)[1]), "=r"((r)[2]), "=r"((r)[3]) : "r"(addr))

__device__ __forceinline__ void mma_bf16(float* c, const uint32_t* a, const uint32_t* b) {
    asm volatile(
        "mma.sync.aligned.m16n8k16.row.col.f32.bf16.bf16.f32 "
        "{%0,%1,%2,%3}, {%4,%5,%6,%7}, {%8,%9}, {%0,%1,%2,%3};"
        : "+f"(c[0]), "+f"(c[1]), "+f"(c[2]), "+f"(c[3])
        : "r"(a[0]), "r"(a[1]), "r"(a[2]), "r"(a[3]), "r"(b[0]), "r"(b[1]));
}

__device__ __forceinline__ void split2(float a, float b, uint32_t& hi, uint32_t& lo) {
    __nv_bfloat16 h0 = __float2bfloat16(a), h1 = __float2bfloat16(b);
    __nv_bfloat16 l0 = __float2bfloat16(a - __bfloat162float(h0));
    __nv_bfloat16 l1 = __float2bfloat16(b - __bfloat162float(h1));
    __nv_bfloat16 hh[2] = {h0, h1}, ll[2] = {l0, l1};
    hi = *(uint32_t*)hh;
    lo = *(uint32_t*)ll;
}

// ---------------------------------------------------------------------------
// Prep kernels
// ---------------------------------------------------------------------------
__global__ __launch_bounds__(256) void prep_x_kernel(
    const float* __restrict__ x, __nv_bfloat16* __restrict__ xh,
    __nv_bfloat16* __restrict__ xl)
{
    int i = blockIdx.x * 256 + threadIdx.x;
    float4 v = ((const float4*)x)[i];
    float f[4] = {v.x, v.y, v.z, v.w};
    __nv_bfloat16 h[4], l[4];
#pragma unroll
    for (int j = 0; j < 4; j++) {
        h[j] = __float2bfloat16(f[j]);
        l[j] = __float2bfloat16(f[j] - __bfloat162float(h[j]));
    }
    *(uint2*)(xh + 4 * (size_t)i) = *(uint2*)h;
    *(uint2*)(xl + 4 * (size_t)i) = *(uint2*)l;
}

__global__ __launch_bounds__(256) void prep_w_kernel(
    const float* __restrict__ W, __nv_bfloat16* __restrict__ th,
    __nv_bfloat16* __restrict__ tl)
{
    __shared__ float t[32][33];
    const int mat = blockIdx.z;
    const int nb = blockIdx.x * 32, kb = blockIdx.y * 32;
    const int tx = threadIdx.x, ty = threadIdx.y;
    const float* src = W + (size_t)mat * 65536;
#pragma unroll
    for (int i = 0; i < 4; i++)
        t[ty + 8 * i][tx] = src[(size_t)(kb + ty + 8 * i) * 256 + nb + tx];
    __syncthreads();
#pragma unroll
    for (int i = 0; i < 4; i++) {
        float v = t[tx][ty + 8 * i];
        size_t idx = (size_t)mat * 65536 + (size_t)(nb + ty + 8 * i) * 256 + kb + tx;
        __nv_bfloat16 h = __float2bfloat16(v);
        th[idx] = h;
        tl[idx] = __float2bfloat16(v - __bfloat162float(h));
    }
}

// W1 [31][256][50] -> [31][64][256] bf16 hi/lo  (out n-major, pad to 64)
__global__ __launch_bounds__(256) void prep_w1_kernel(
    const float* __restrict__ W1, __nv_bfloat16* __restrict__ th,
    __nv_bfloat16* __restrict__ tl)
{
    int idx = blockIdx.x * 256 + threadIdx.x;
    int k = idx & 255, j = (idx >> 8) & 63, n = idx >> 14;
    float v = (j < HDIM) ? W1[((size_t)n * 256 + k) * HDIM + j] : 0.f;
    __nv_bfloat16 h = __float2bfloat16(v);
    th[idx] = h;
    tl[idx] = __float2bfloat16(v - __bfloat162float(h));
}

// Ww [31][50][256] -> [31][256][64] bf16 hi/lo (pad k to 64)
__global__ __launch_bounds__(256) void prep_ww_kernel(
    const float* __restrict__ Ww, __nv_bfloat16* __restrict__ th,
    __nv_bfloat16* __restrict__ tl)
{
    int idx = blockIdx.x * 256 + threadIdx.x;
    int j = idx & 63, d = (idx >> 6) & 255, n = idx >> 14;
    float v = (j < HDIM) ? Ww[((size_t)n * HDIM + j) * 256 + d] : 0.f;
    __nv_bfloat16 h = __float2bfloat16(v);
    th[idx] = h;
    tl[idx] = __float2bfloat16(v - __bfloat162float(h));
}

__global__ __launch_bounds__(256) void zero_kernel(float* __restrict__ p) {
    int i = blockIdx.x * 256 + threadIdx.x;
    ((float4*)p)[i] = make_float4(0.f, 0.f, 0.f, 0.f);
}

// ---------------------------------------------------------------------------
// mma.sync GEMM: C[64,128] tile of A[8192,256] @ B[mat]^T (B stored [N][K]).
// bf16 hi/lo 3-MMA, fp32 accumulate. 3-stage cp.async pipeline, 1 sync/chunk.
// Warps: 2m x 4n (warp tile 32x32).
// MODE 0 (encoder): relu(C+bias) -> bf16 hi/lo
// MODE 1 (leaf):    atomicAdd(yleaf, sum_n relu(C+b1)*W2)
// ---------------------------------------------------------------------------
#define ST_AH 0
#define ST_AL 5120
#define ST_BH 10240
#define ST_BL 20480
#define ST_SZ 30720
#define MM_SMEM (3 * ST_SZ + 1024)

template <int MODE>
__global__ __launch_bounds__(256, 2) void mm_kernel(
    const __nv_bfloat16* __restrict__ Ah, const __nv_bfloat16* __restrict__ Al,
    const __nv_bfloat16* __restrict__ Bh, const __nv_bfloat16* __restrict__ Bl,
    const float* __restrict__ bias, const float* __restrict__ w2,
    __nv_bfloat16* __restrict__ oh, __nv_bfloat16* __restrict__ ol,
    float* __restrict__ yleaf)
{
    extern __shared__ char smem[];
    const uint32_t sbase = smem_u32(smem);
    const int tid = threadIdx.x;
    const int lane = tid & 31, warp = tid >> 5;
    const int m0 = blockIdx.x * 64;
    const int n0 = blockIdx.y * 128;
    const int mat = blockIdx.z;
    const int wm = (warp >> 2) * 32;   // {0,32}
    const int wn = (warp & 3) * 32;    // {0,32,64,96}

    const __nv_bfloat16* bhp = Bh + (size_t)mat * 65536;
    const __nv_bfloat16* blp = Bl + (size_t)mat * 65536;

    float* s_bias = (float*)(smem + 3 * ST_SZ);
    float* s_w2   = (float*)(smem + 3 * ST_SZ + 512);
    if (MODE == 1 && tid < 128) {
        s_bias[tid] = bias[(size_t)mat * 256 + n0 + tid];
        s_w2[tid]   = w2[(size_t)mat * 256 + n0 + tid];
    }

    float c[2][4][4];
#pragma unroll
    for (int mf = 0; mf < 2; mf++)
#pragma unroll
        for (int nf = 0; nf < 4; nf++)
#pragma unroll
            for (int q = 0; q < 4; q++) c[mf][nf][q] = 0.f;

    const int crow = tid >> 2;
    const int cu   = tid & 3;
    const int arow = (lane & 7) + ((lane >> 3) & 1) * 8;
    const int acol = (lane >> 4) * 8;
    const int brow = (lane & 7) + (lane >> 4) * 8;
    const int bcol = ((lane >> 3) & 1) * 8;

#define ISSUE_CHUNK(CI) do {                                                    \
    const int k0_ = (CI) * 32;                                                  \
    const uint32_t st_ = sbase + ((CI) % 3) * ST_SZ;                            \
    const uint32_t da = st_ + crow * 80 + cu * 16;                              \
    const size_t ga = (size_t)(m0 + crow) * 256 + k0_ + cu * 8;                 \
    const size_t gb = (size_t)(n0 + crow) * 256 + k0_ + cu * 8;                 \
    CP_ASYNC16(da,          Ah + ga);                                           \
    CP_ASYNC16(da + ST_AL,  Al + ga);                                           \
    CP_ASYNC16(st_ + ST_BH + crow * 80 + cu * 16,        bhp + gb);             \
    CP_ASYNC16(st_ + ST_BH + (crow + 64) * 80 + cu * 16, bhp + gb + 64 * 256);  \
    CP_ASYNC16(st_ + ST_BL + crow * 80 + cu * 16,        blp + gb);             \
    CP_ASYNC16(st_ + ST_BL + (crow + 64) * 80 + cu * 16, blp + gb + 64 * 256);  \
    CP_COMMIT();                                                                \
} while (0)

    ISSUE_CHUNK(0);
    ISSUE_CHUNK(1);

#pragma unroll 1
    for (int ci = 0; ci < 8; ci++) {
        if (ci < 7) CP_WAIT1(); else CP_WAIT0();
        __syncthreads();
        if (ci < 6) ISSUE_CHUNK(ci + 2);

        const uint32_t st = sbase + (ci % 3) * ST_SZ;
#pragma unroll
        for (int kk = 0; kk < 32; kk += 16) {
            uint32_t ah[2][4], al[2][4];
#pragma unroll
            for (int mf = 0; mf < 2; mf++) {
                uint32_t addr = st + (wm + mf * 16 + arow) * 80 + (kk + acol) * 2;
                LDSM4(ah[mf], addr);
                LDSM4(al[mf], addr + ST_AL);
            }
            uint32_t bhf[4][2], blf[4][2];
#pragma unroll
            for (int np = 0; np < 2; np++) {
                uint32_t addr = st + ST_BH
                              + (wn + np * 16 + brow) * 80 + (kk + bcol) * 2;
                uint32_t r[4];
                LDSM4(r, addr);
                bhf[2 * np][0] = r[0]; bhf[2 * np][1] = r[1];
                bhf[2 * np + 1][0] = r[2]; bhf[2 * np + 1][1] = r[3];
                LDSM4(r, addr + (ST_BL - ST_BH));
                blf[2 * np][0] = r[0]; blf[2 * np][1] = r[1];
                blf[2 * np + 1][0] = r[2]; blf[2 * np + 1][1] = r[3];
            }
#pragma unroll
            for (int mf = 0; mf < 2; mf++)
#pragma unroll
                for (int nf = 0; nf < 4; nf++) {
                    mma_bf16(c[mf][nf], ah[mf], bhf[nf]);
                    mma_bf16(c[mf][nf], ah[mf], blf[nf]);
                    mma_bf16(c[mf][nf], al[mf], bhf[nf]);
                }
        }
    }
#undef ISSUE_CHUNK

    const int erow = lane >> 2;
    const int ecol = (lane & 3) * 2;

    if (MODE == 0) {
#pragma unroll
        for (int mf = 0; mf < 2; mf++) {
            const int gr0 = m0 + wm + mf * 16 + erow;
#pragma unroll
            for (int nf = 0; nf < 4; nf++) {
                const int gc = n0 + wn + nf * 8 + ecol;
                float2 bb = *(const float2*)&bias[gc];
                float v00 = fmaxf(c[mf][nf][0] + bb.x, 0.f);
                float v01 = fmaxf(c[mf][nf][1] + bb.y, 0.f);
                float v10 = fmaxf(c[mf][nf][2] + bb.x, 0.f);
                float v11 = fmaxf(c[mf][nf][3] + bb.y, 0.f);
                const size_t i0 = (size_t)gr0 * 256 + gc;
                const size_t i1 = (size_t)(gr0 + 8) * 256 + gc;
                uint32_t h0, l0, h1, l1;
                split2(v00, v01, h0, l0);
                split2(v10, v11, h1, l1);
                *(uint32_t*)(oh + i0) = h0;
                *(uint32_t*)(oh + i1) = h1;
                *(uint32_t*)(ol + i0) = l0;
                *(uint32_t*)(ol + i1) = l1;
            }
        }
    } else {
        float part[2][2] = {{0.f, 0.f}, {0.f, 0.f}};
#pragma unroll
        for (int mf = 0; mf < 2; mf++)
#pragma unroll
            for (int nf = 0; nf < 4; nf++) {
                const int lc = wn + nf * 8 + ecol;
                const float b0s = s_bias[lc], b1s = s_bias[lc + 1];
                const float w0 = s_w2[lc], w1 = s_w2[lc + 1];
                part[mf][0] = fmaf(fmaxf(c[mf][nf][0] + b0s, 0.f), w0, part[mf][0]);
                part[mf][0] = fmaf(fmaxf(c[mf][nf][1] + b1s, 0.f), w1, part[mf][0]);
                part[mf][1] = fmaf(fmaxf(c[mf][nf][2] + b0s, 0.f), w0, part[mf][1]);
                part[mf][1] = fmaf(fmaxf(c[mf][nf][3] + b1s, 0.f), w1, part[mf][1]);
            }
#pragma unroll
        for (int mf = 0; mf < 2; mf++)
#pragma unroll
            for (int h = 0; h < 2; h++) {
                part[mf][h] += __shfl_xor_sync(0xffffffffu, part[mf][h], 1);
                part[mf][h] += __shfl_xor_sync(0xffffffffu, part[mf][h], 2);
            }
        if ((lane & 3) == 0) {
#pragma unroll
            for (int mf = 0; mf < 2; mf++)
#pragma unroll
                for (int h = 0; h < 2; h++) {
                    const int row = m0 + wm + mf * 16 + h * 8 + erow;
                    atomicAdd(&yleaf[(size_t)mat * BATCH + row], part[mf][h]);
                }
        }
    }
}

// ---------------------------------------------------------------------------
// Inner-node kernel via mma.sync. Per (m-tile 64 rows, node n):
//  Phase A: H[64,64] = relu(emb@W1t^T + b1)   (K=256, 3-stage cp.async)
//  Phase B: z[64,256] = H@Wwt^T + bw          (K=64, Ww streamed from L2,
//                                              3-stage cp.async)
//  Epilogue: softmax over 256, dot with x, Wb/Wbeta dots, sigmoid -> pR
// ---------------------------------------------------------------------------
#define IA_SZ  20480                 // Ah 0 | Al 5120 | W1h 10240 | W1l 15360
#define IB_SZ  24576                 // Bh 0 (256x48) | Bl 12288
#define IN_HH  73728                 // 64 x 144
#define IN_HL  82944
#define IN_RED 92160                 // 3 x 2 x 64 floats
#define IN_WBS 93696
#define IN_WBTS 93952
#define IN_SMEM 94208

__global__ __launch_bounds__(256, 2) void inner_mma_kernel(
    const __nv_bfloat16* __restrict__ eh, const __nv_bfloat16* __restrict__ el,
    const __nv_bfloat16* __restrict__ w1h, const __nv_bfloat16* __restrict__ w1l,
    const __nv_bfloat16* __restrict__ wwh, const __nv_bfloat16* __restrict__ wwl,
    const float* __restrict__ x, const float* __restrict__ b1,
    const float* __restrict__ bw, const float* __restrict__ Wb,
    const float* __restrict__ bb, const float* __restrict__ Wbt,
    const float* __restrict__ bbt, float* __restrict__ pR)
{
    extern __shared__ char smem[];
    const uint32_t sb = smem_u32(smem);
    const int tid = threadIdx.x, lane = tid & 31, w = tid >> 5;
    const int n = blockIdx.y, m0 = blockIdx.x * 64;

    float* sWb  = (float*)(smem + IN_WBS);
    float* sWbt = (float*)(smem + IN_WBTS);
    if (tid < HDIM)                sWb[tid] = Wb[n * HDIM + tid];
    else if (tid < 2 * HDIM)       sWbt[tid - HDIM] = Wbt[n * HDIM + tid - HDIM];

    const int crow = tid >> 2, cu = tid & 3;
    const __nv_bfloat16* w1hp = w1h + (size_t)n * 64 * 256;
    const __nv_bfloat16* w1lp = w1l + (size_t)n * 64 * 256;
    const __nv_bfloat16* wwhp = wwh + (size_t)n * 256 * 64;
    const __nv_bfloat16* wwlp = wwl + (size_t)n * 256 * 64;

#define IN_ISSUE(CI) do {                                           \
    const int k0_ = (CI) * 32;                                      \
    const uint32_t st_ = sb + ((CI) % 3) * IA_SZ;                   \
    const uint32_t d = st_ + crow * 80 + cu * 16;                   \
    const size_t ga = (size_t)(m0 + crow) * 256 + k0_ + cu * 8;     \
    const size_t gw = (size_t)crow * 256 + k0_ + cu * 8;            \
    CP_ASYNC16(d,         eh + ga);                                 \
    CP_ASYNC16(d + 5120,  el + ga);                                 \
    CP_ASYNC16(d + 10240, w1hp + gw);                               \
    CP_ASYNC16(d + 15360, w1lp + gw);                               \
    CP_COMMIT();                                                    \
} while (0)

    const int arow = (lane & 7) + ((lane >> 3) & 1) * 8;
    const int acol = (lane >> 4) * 8;
    const int brow = (lane & 7) + (lane >> 4) * 8;
    const int bcol = ((lane >> 3) & 1) * 8;

    // ---- Phase A ----
    const int wmA = (w >> 1) * 16, wnA = (w & 1) * 32;
    float accA[4][4];
#pragma unroll
    for (int i = 0; i < 4; i++)
#pragma unroll
        for (int q = 0; q < 4; q++) accA[i][q] = 0.f;

    IN_ISSUE(0);
    IN_ISSUE(1);

#pragma unroll 1
    for (int ci = 0; ci < 8; ci++) {
        if (ci < 7) CP_WAIT1(); else CP_WAIT0();
        __syncthreads();
        if (ci < 6) IN_ISSUE(ci + 2);

        const uint32_t st = sb + (ci % 3) * IA_SZ;
#pragma unroll
        for (int kk = 0; kk < 32; kk += 16) {
            uint32_t ah[4], al[4];
            const uint32_t aaddr = st + (wmA + arow) * 80 + (kk + acol) * 2;
            LDSM4(ah, aaddr);
            LDSM4(al, aaddr + 5120);
            uint32_t bh[4][2], bl[4][2];
#pragma unroll
            for (int g = 0; g < 2; g++) {
                const uint32_t baddr = st + 10240
                    + (wnA + g * 16 + brow) * 80 + (kk + bcol) * 2;
                uint32_t r[4];
                LDSM4(r, baddr);
                bh[2 * g][0] = r[0]; bh[2 * g][1] = r[1];
                bh[2 * g + 1][0] = r[2]; bh[2 * g + 1][1] = r[3];
                LDSM4(r, baddr + 5120);
                bl[2 * g][0] = r[0]; bl[2 * g][1] = r[1];
                bl[2 * g + 1][0] = r[2]; bl[2 * g + 1][1] = r[3];
            }
#pragma unroll
            for (int nf = 0; nf < 4; nf++) {
                mma_bf16(accA[nf], ah, bh[nf]);
                mma_bf16(accA[nf], ah, bl[nf]);
                mma_bf16(accA[nf], al, bh[nf]);
            }
        }
    }
#undef IN_ISSUE

    // Phase A epilogue: relu(+b1), split, store H to smem
    {
        const int r0 = wmA + (lane >> 2);
#pragma unroll
        for (int nf = 0; nf < 4; nf++) {
            const int col = wnA + nf * 8 + (lane & 3) * 2;
            const float bb0 = (col < HDIM)     ? b1[n * HDIM + col]     : 0.f;
            const float bb1 = (col + 1 < HDIM) ? b1[n * HDIM + col + 1] : 0.f;
            float v00 = fmaxf(accA[nf][0] + bb0, 0.f);
            float v01 = fmaxf(accA[nf][1] + bb1, 0.f);
            float v10 = fmaxf(accA[nf][2] + bb0, 0.f);
            float v11 = fmaxf(accA[nf][3] + bb1, 0.f);
            uint32_t h0, l0, h1, l1;
            split2(v00, v01, h0, l0);
            split2(v10, v11, h1, l1);
            *(uint32_t*)(smem + IN_HH + r0 * 144 + col * 2) = h0;
            *(uint32_t*)(smem + IN_HL + r0 * 144 + col * 2) = l0;
            *(uint32_t*)(smem + IN_HH + (r0 + 8) * 144 + col * 2) = h1;
            *(uint32_t*)(smem + IN_HL + (r0 + 8) * 144 + col * 2) = l1;
        }
    }
    __syncthreads();

    // ---- Phase B: z[64,256] = H @ Wwt^T, Ww streamed from L2 ----
#define IN_ISSUE_B(KK) do {                                         \
    const uint32_t st_ = sb + ((KK) % 3) * IB_SZ;                   \
    const uint32_t d = st_ + tid * 48;                              \
    const size_t g = (size_t)tid * 64 + (KK) * 16;                  \
    CP_ASYNC16(d,          wwhp + g);                               \
    CP_ASYNC16(d + 16,     wwhp + g + 8);                           \
    CP_ASYNC16(d + 12288,      wwlp + g);                           \
    CP_ASYNC16(d + 12288 + 16, wwlp + g + 8);                       \
    CP_COMMIT();                                                    \
} while (0)

    const int wmB = (w >> 1) * 16, wnB = (w & 1) * 128;
    float z[16][4];
#pragma unroll
    for (int nf = 0; nf < 16; nf++)
#pragma unroll
        for (int q = 0; q < 4; q++) z[nf][q] = 0.f;

    IN_ISSUE_B(0);
    IN_ISSUE_B(1);

#pragma unroll 1
    for (int kk = 0; kk < 4; kk++) {
        if (kk < 3) CP_WAIT1(); else CP_WAIT0();
        __syncthreads();
        if (kk < 2) IN_ISSUE_B(kk + 2);

        const uint32_t st = sb + (kk % 3) * IB_SZ;
        uint32_t ah[4], al[4];
        const uint32_t aaddr = sb + IN_HH + (wmB + arow) * 144 + (kk * 16 + acol) * 2;
        LDSM4(ah, aaddr);
        LDSM4(al, aaddr + (IN_HL - IN_HH));
#pragma unroll
        for (int g = 0; g < 8; g++) {
            const uint32_t baddr = st + (wnB + g * 16 + brow) * 48 + bcol * 2;
            uint32_t rh[4], rl[4];
            LDSM4(rh, baddr);
            LDSM4(rl, baddr + 12288);
            uint32_t b0h[2] = {rh[0], rh[1]}, b1h[2] = {rh[2], rh[3]};
            uint32_t b0l[2] = {rl[0], rl[1]}, b1l[2] = {rl[2], rl[3]};
            mma_bf16(z[2 * g],     ah, b0h);
            mma_bf16(z[2 * g],     ah, b0l);
            mma_bf16(z[2 * g],     al, b0h);
            mma_bf16(z[2 * g + 1], ah, b1h);
            mma_bf16(z[2 * g + 1], ah, b1l);
            mma_bf16(z[2 * g + 1], al, b1h);
        }
    }
#undef IN_ISSUE_B

    // ---- Phase B epilogue ----
    float* redmax = (float*)(smem + IN_RED);       // [2][64]
    float* redse  = redmax + 128;                  // [2][64]
    float* redsx  = redse + 128;                   // [2][64]

    const int r0 = wmB + (lane >> 2), r1 = r0 + 8;
    float mx0 = -1e30f, mx1 = -1e30f;
#pragma unroll
    for (int nf = 0; nf < 16; nf++) {
        const int col = wnB + nf * 8 + (lane & 3) * 2;
        float2 bwv = *(const float2*)&bw[n * 256 + col];
        z[nf][0] += bwv.x; z[nf][1] += bwv.y;
        z[nf][2] += bwv.x; z[nf][3] += bwv.y;
        mx0 = fmaxf(mx0, fmaxf(z[nf][0], z[nf][1]));
        mx1 = fmaxf(mx1, fmaxf(z[nf][2], z[nf][3]));
    }
    mx0 = fmaxf(mx0, __shfl_xor_sync(0xffffffffu, mx0, 1));
    mx0 = fmaxf(mx0, __shfl_xor_sync(0xffffffffu, mx0, 2));
    mx1 = fmaxf(mx1, __shfl_xor_sync(0xffffffffu, mx1, 1));
    mx1 = fmaxf(mx1, __shfl_xor_sync(0xffffffffu, mx1, 2));
    if ((lane & 3) == 0) {
        redmax[(w & 1) * 64 + r0] = mx0;
        redmax[(w & 1) * 64 + r1] = mx1;
    }
    __syncthreads();
    mx0 = fmaxf(redmax[r0], redmax[64 + r0]);
    mx1 = fmaxf(redmax[r1], redmax[64 + r1]);

    float se0 = 0.f, sx0 = 0.f, se1 = 0.f, sx1 = 0.f;
    const float* x0 = x + (size_t)(m0 + r0) * 256;
    const float* x1 = x + (size_t)(m0 + r1) * 256;
#pragma unroll
    for (int nf = 0; nf < 16; nf++) {
        const int col = wnB + nf * 8 + (lane & 3) * 2;
        float2 xv0 = *(const float2*)&x0[col];
        float2 xv1 = *(const float2*)&x1[col];
        float e;
        e = __expf(z[nf][0] - mx0); se0 += e; sx0 = fmaf(e, xv0.x, sx0);
        e = __expf(z[nf][1] - mx0); se0 += e; sx0 = fmaf(e, xv0.y, sx0);
        e = __expf(z[nf][2] - mx1); se1 += e; sx1 = fmaf(e, xv1.x, sx1);
        e = __expf(z[nf][3] - mx1); se1 += e; sx1 = fmaf(e, xv1.y, sx1);
    }
#pragma unroll
    for (int off = 1; off <= 2; off <<= 1) {
        se0 += __shfl_xor_sync(0xffffffffu, se0, off);
        sx0 += __shfl_xor_sync(0xffffffffu, sx0, off);
        se1 += __shfl_xor_sync(0xffffffffu, se1, off);
        sx1 += __shfl_xor_sync(0xffffffffu, sx1, off);
    }
    if ((lane & 3) == 0) {
        redse[(w & 1) * 64 + r0] = se0; redse[(w & 1) * 64 + r1] = se1;
        redsx[(w & 1) * 64 + r0] = sx0; redsx[(w & 1) * 64 + r1] = sx1;
    }
    __syncthreads();

    if ((w & 1) == 0) {
        float pb0 = 0.f, pbt0 = 0.f, pb1 = 0.f, pbt1 = 0.f;
        for (int j = (lane & 3); j < HDIM; j += 4) {
            float h0 = __bfloat162float(*(const __nv_bfloat16*)(smem + IN_HH + r0 * 144 + j * 2))
                     + __bfloat162float(*(const __nv_bfloat16*)(smem + IN_HL + r0 * 144 + j * 2));
            float h1 = __bfloat162float(*(const __nv_bfloat16*)(smem + IN_HH + r1 * 144 + j * 2))
                     + __bfloat162float(*(const __nv_bfloat16*)(smem + IN_HL + r1 * 144 + j * 2));
            pb0  = fmaf(h0, sWb[j],  pb0);
            pbt0 = fmaf(h0, sWbt[j], pbt0);
            pb1  = fmaf(h1, sWb[j],  pb1);
            pbt1 = fmaf(h1, sWbt[j], pbt1);
        }
#pragma unroll
        for (int off = 1; off <= 2; off <<= 1) {
            pb0  += __shfl_xor_sync(0xffffffffu, pb0, off);
            pbt0 += __shfl_xor_sync(0xffffffffu, pbt0, off);
            pb1  += __shfl_xor_sync(0xffffffffu, pb1, off);
            pbt1 += __shfl_xor_sync(0xffffffffu, pbt1, off);
        }
        if ((lane & 3) == 0) {
            const float bbn = bb[n], bbtn = bbt[n];
            float seA = redse[r0] + redse[64 + r0];
            float sxA = redsx[r0] + redsx[64 + r0];
            float val = (pbt0 + bbtn) * (sxA / seA + pb0 + bbn);
            pR[(size_t)n * BATCH + m0 + r0] = 1.f / (1.f + __expf(-val));
            seA = redse[r1] + redse[64 + r1];
            sxA = redsx[r1] + redsx[64 + r1];
            val = (pbt1 + bbtn) * (sxA / seA + pb1 + bbn);
            pR[(size_t)n * BATCH + m0 + r1] = 1.f / (1.f + __expf(-val));
        }
    }
}

// ---------------------------------------------------------------------------
// Combine: out[b] = sum_leaf prob(leaf,b) * (y_leaf[leaf,b] + b2[leaf])
// ---------------------------------------------------------------------------
__global__ __launch_bounds__(256) void combine_kernel(
    const float* __restrict__ pR, const float* __restrict__ yl,
    const float* __restrict__ b2, float* __restrict__ out)
{
    const int b = blockIdx.x * 256 + threadIdx.x;
    float p[N_INNER];
#pragma unroll
    for (int i = 0; i < N_INNER; i++) p[i] = pR[(size_t)i * BATCH + b];

    float prob[N_LEAF];
    prob[0] = 1.f;
#pragma unroll
    for (int lev = 0; lev < 5; lev++) {
        const int cnt = 1 << lev;
        const int off = cnt - 1;
#pragma unroll
        for (int i = N_LEAF - 1; i >= 0; i--) {
            if (i < cnt) {
                float pr   = p[off + i];
                float base = prob[i];
                prob[2 * i]     = base * (1.f - pr);
                prob[2 * i + 1] = base * pr;
            }
        }
    }
    float acc = 0.f;
#pragma unroll
    for (int l = 0; l < N_LEAF; l++)
        acc = fmaf(prob[l], yl[(size_t)l * BATCH + b] + b2[l], acc);
    out[b] = acc;
}

// ---------------------------------------------------------------------------
extern "C" void kernel_launch(void* const* d_in, const int* in_sizes, int n_in,
                              void* d_out, int out_size)
{
    const float* x       = (const float*)d_in[0];
    const float* enc_W   = (const float*)d_in[1];
    const float* enc_b   = (const float*)d_in[2];
    const float* in_W1   = (const float*)d_in[3];
    const float* in_b1   = (const float*)d_in[4];
    const float* in_Ww   = (const float*)d_in[5];
    const float* in_bw   = (const float*)d_in[6];
    const float* in_Wb   = (const float*)d_in[7];
    const float* in_bb   = (const float*)d_in[8];
    const float* in_Wbt  = (const float*)d_in[9];
    const float* in_bbt  = (const float*)d_in[10];
    const float* lf_W1   = (const float*)d_in[11];
    const float* lf_b1   = (const float*)d_in[12];
    const float* lf_W2   = (const float*)d_in[13];
    const float* lf_b2   = (const float*)d_in[14];
    float* out = (float*)d_out;

    float *pR, *yl;
    __nv_bfloat16 *xh, *xl, *e0h, *e0l, *e1h, *e1l, *wth, *wtl;
    __nv_bfloat16 *w1th, *w1tl, *wwth, *wwtl;
    cudaGetSymbolAddress((void**)&pR,  g_pR);
    cudaGetSymbolAddress((void**)&yl,  g_yleaf);
    cudaGetSymbolAddress((void**)&xh,  g_xh);
    cudaGetSymbolAddress((void**)&xl,  g_xl);
    cudaGetSymbolAddress((void**)&e0h, g_e0h);
    cudaGetSymbolAddress((void**)&e0l, g_e0l);
    cudaGetSymbolAddress((void**)&e1h, g_e1h);
    cudaGetSymbolAddress((void**)&e1l, g_e1l);
    cudaGetSymbolAddress((void**)&wth, g_wth);
    cudaGetSymbolAddress((void**)&wtl, g_wtl);
    cudaGetSymbolAddress((void**)&w1th, g_w1th);
    cudaGetSymbolAddress((void**)&w1tl, g_w1tl);
    cudaGetSymbolAddress((void**)&wwth, g_wwth);
    cudaGetSymbolAddress((void**)&wwtl, g_wwtl);

    cudaFuncSetAttribute(mm_kernel<0>, cudaFuncAttributeMaxDynamicSharedMemorySize, MM_SMEM);
    cudaFuncSetAttribute(mm_kernel<1>, cudaFuncAttributeMaxDynamicSharedMemorySize, MM_SMEM);
    cudaFuncSetAttribute(inner_mma_kernel, cudaFuncAttributeMaxDynamicSharedMemorySize, IN_SMEM);

    // --- prep (ordered so launch #4 = mm_kernel encoder L1, for ncu) ---
    prep_x_kernel<<<BATCH * EDIM / 1024, 256>>>(x, xh, xl);
    prep_w_kernel<<<dim3(8, 8, 4),  dim3(32, 8)>>>(enc_W, wth, wtl);
    prep_w_kernel<<<dim3(8, 8, 32), dim3(32, 8)>>>(lf_W1, wth + 4 * 65536, wtl + 4 * 65536);

    // --- encoder L1 (profiled launch) ---
    mm_kernel<0><<<dim3(128, 2, 1), 256, MM_SMEM>>>(xh, xl, wth, wtl,
        enc_b, nullptr, e0h, e0l, nullptr);

    // --- remaining prep ---
    prep_w1_kernel<<<N_INNER * 64, 256>>>(in_W1, w1th, w1tl);
    prep_ww_kernel<<<N_INNER * 64, 256>>>(in_Ww, wwth, wwtl);
    zero_kernel<<<N_LEAF * BATCH / 1024, 256>>>(yl);

    // --- encoder L2-4 ---
    mm_kernel<0><<<dim3(128, 2, 1), 256, MM_SMEM>>>(e0h, e0l, wth + 65536, wtl + 65536,
        enc_b + 256, nullptr, e1h, e1l, nullptr);
    mm_kernel<0><<<dim3(128, 2, 1), 256, MM_SMEM>>>(e1h, e1l, wth + 2 * 65536, wtl + 2 * 65536,
        enc_b + 512, nullptr, e0h, e0l, nullptr);
    mm_kernel<0><<<dim3(128, 2, 1), 256, MM_SMEM>>>(e0h, e0l, wth + 3 * 65536, wtl + 3 * 65536,
        enc_b + 768, nullptr, e1h, e1l, nullptr);

    // --- inner gates (mma.sync, Ww streamed) ---
    inner_mma_kernel<<<dim3(BATCH / 64, N_INNER), 256, IN_SMEM>>>(
        e1h, e1l, w1th, w1tl, wwth, wwtl,
        x, in_b1, in_bw, in_Wb, in_bb, in_Wbt, in_bbt, pR);

    // --- leaves (mma.sync, atomicAdd into yl) ---
    mm_kernel<1><<<dim3(128, 2, N_LEAF), 256, MM_SMEM>>>(
        e1h, e1l, wth + 4 * 65536, wtl + 4 * 65536,
        lf_b1, lf_W2, nullptr, nullptr, yl);

    // --- combine ---
    combine_kernel<<<BATCH / 256, 256>>>(pR, yl, lf_b2, out);
}

// round 6
// speedup vs baseline: 1.0869x; 1.0869x over previous
#include <cuda_runtime.h>
#include <cuda_bf16.h>
#include <cstdint>
#include <math.h>

#define BATCH 8192
#define EDIM  256
#define HDIM  50
#define N_INNER 31
#define N_LEAF  32

// ---------------------------------------------------------------------------
// Device scratch
// ---------------------------------------------------------------------------
__device__ float g_pR[N_INNER * BATCH];
__device__ float g_yleaf[N_LEAF * BATCH];

__device__ __nv_bfloat16 g_xh[BATCH * EDIM];
__device__ __nv_bfloat16 g_xl[BATCH * EDIM];
__device__ __nv_bfloat16 g_e0h[BATCH * EDIM];
__device__ __nv_bfloat16 g_e0l[BATCH * EDIM];
__device__ __nv_bfloat16 g_e1h[BATCH * EDIM];
__device__ __nv_bfloat16 g_e1l[BATCH * EDIM];
// transposed weights: 0..3 encoder, 4..35 leaves. layout [mat][N=256][K=256]
__device__ __nv_bfloat16 g_wth[36 * 65536];
__device__ __nv_bfloat16 g_wtl[36 * 65536];
// inner: W1 transposed [31][64][256] (rows 50..63 zero)
__device__ __nv_bfloat16 g_w1th[N_INNER * 64 * 256];
__device__ __nv_bfloat16 g_w1tl[N_INNER * 64 * 256];
// inner: Ww transposed [31][256][64] (cols 50..63 zero)
__device__ __nv_bfloat16 g_wwth[N_INNER * 256 * 64];
__device__ __nv_bfloat16 g_wwtl[N_INNER * 256 * 64];

// ---------------------------------------------------------------------------
// Helpers
// ---------------------------------------------------------------------------
__device__ __forceinline__ uint32_t smem_u32(const void* p) {
    uint32_t a;
    asm("{ .reg .u64 t; cvta.to.shared.u64 t, %1; cvt.u32.u64 %0, t; }" : "=r"(a) : "l"(p));
    return a;
}
#define CP_ASYNC16(dst, src) \
    asm volatile("cp.async.cg.shared.global [%0], [%1], 16;" :: "r"(dst), "l"(src) : "memory")
#define CP_COMMIT() asm volatile("cp.async.commit_group;" ::: "memory")
#define CP_WAIT1()  asm volatile("cp.async.wait_group 1;" ::: "memory")
#define CP_WAIT0()  asm volatile("cp.async.wait_group 0;" ::: "memory")

#define LDSM4(r, addr) \
    asm volatile("ldmatrix.sync.aligned.m8n8.x4.shared.b16 {%0,%1,%2,%3}, [%4];" \
        : "=r"((r)[0]), "=r"((r)[1]), "=r"((r)[2]), "=r"((r)[3]) : "r"(addr))

__device__ __forceinline__ void mma_bf16(float* c, const uint32_t* a, const uint32_t* b) {
    asm volatile(
        "mma.sync.aligned.m16n8k16.row.col.f32.bf16.bf16.f32 "
        "{%0,%1,%2,%3}, {%4,%5,%6,%7}, {%8,%9}, {%0,%1,%2,%3};"
        : "+f"(c[0]), "+f"(c[1]), "+f"(c[2]), "+f"(c[3])
        : "r"(a[0]), "r"(a[1]), "r"(a[2]), "r"(a[3]), "r"(b[0]), "r"(b[1]));
}

__device__ __forceinline__ void split2(float a, float b, uint32_t& hi, uint32_t& lo) {
    __nv_bfloat16 h0 = __float2bfloat16(a), h1 = __float2bfloat16(b);
    __nv_bfloat16 l0 = __float2bfloat16(a - __bfloat162float(h0));
    __nv_bfloat16 l1 = __float2bfloat16(b - __bfloat162float(h1));
    __nv_bfloat16 hh[2] = {h0, h1}, ll[2] = {l0, l1};
    hi = *(uint32_t*)hh;
    lo = *(uint32_t*)ll;
}

// ---------------------------------------------------------------------------
// Merged elementwise prep: x split | W1 transpose+split | Ww transpose+split
// | zero yleaf.  Region by blockIdx.x.
// ---------------------------------------------------------------------------
#define PS_X   2048                      // 8192*256/4/256
#define PS_W1  (PS_X + 1984)             // 31*64*256/256
#define PS_WW  (PS_W1 + 1984)
#define PS_Z   (PS_WW + 256)             // 32*8192/4/256

__global__ __launch_bounds__(256) void prep_small_kernel(
    const float* __restrict__ x, __nv_bfloat16* __restrict__ xh,
    __nv_bfloat16* __restrict__ xl,
    const float* __restrict__ W1, __nv_bfloat16* __restrict__ w1h,
    __nv_bfloat16* __restrict__ w1l,
    const float* __restrict__ Ww, __nv_bfloat16* __restrict__ wwh,
    __nv_bfloat16* __restrict__ wwl,
    float* __restrict__ yl)
{
    const int bid = blockIdx.x;
    if (bid < PS_X) {
        int i = bid * 256 + threadIdx.x;
        float4 v = ((const float4*)x)[i];
        float f[4] = {v.x, v.y, v.z, v.w};
        __nv_bfloat16 h[4], l[4];
#pragma unroll
        for (int j = 0; j < 4; j++) {
            h[j] = __float2bfloat16(f[j]);
            l[j] = __float2bfloat16(f[j] - __bfloat162float(h[j]));
        }
        *(uint2*)(xh + 4 * (size_t)i) = *(uint2*)h;
        *(uint2*)(xl + 4 * (size_t)i) = *(uint2*)l;
    } else if (bid < PS_W1) {
        int idx = (bid - PS_X) * 256 + threadIdx.x;
        int k = idx & 255, j = (idx >> 8) & 63, n = idx >> 14;
        float v = (j < HDIM) ? W1[((size_t)n * 256 + k) * HDIM + j] : 0.f;
        __nv_bfloat16 h = __float2bfloat16(v);
        w1h[idx] = h;
        w1l[idx] = __float2bfloat16(v - __bfloat162float(h));
    } else if (bid < PS_WW) {
        int idx = (bid - PS_W1) * 256 + threadIdx.x;
        int j = idx & 63, d = (idx >> 6) & 255, n = idx >> 14;
        float v = (j < HDIM) ? Ww[((size_t)n * HDIM + j) * 256 + d] : 0.f;
        __nv_bfloat16 h = __float2bfloat16(v);
        wwh[idx] = h;
        wwl[idx] = __float2bfloat16(v - __bfloat162float(h));
    } else {
        int i = (bid - PS_WW) * 256 + threadIdx.x;
        ((float4*)yl)[i] = make_float4(0.f, 0.f, 0.f, 0.f);
    }
}

// ---------------------------------------------------------------------------
// prep_w: transpose [K][N] f32 -> [N][K] bf16 hi/lo per 256x256 matrix
// ---------------------------------------------------------------------------
__global__ __launch_bounds__(256) void prep_w_kernel(
    const float* __restrict__ W, __nv_bfloat16* __restrict__ th,
    __nv_bfloat16* __restrict__ tl)
{
    __shared__ float t[32][33];
    const int mat = blockIdx.z;
    const int nb = blockIdx.x * 32, kb = blockIdx.y * 32;
    const int tx = threadIdx.x, ty = threadIdx.y;
    const float* src = W + (size_t)mat * 65536;
#pragma unroll
    for (int i = 0; i < 4; i++)
        t[ty + 8 * i][tx] = src[(size_t)(kb + ty + 8 * i) * 256 + nb + tx];
    __syncthreads();
#pragma unroll
    for (int i = 0; i < 4; i++) {
        float v = t[tx][ty + 8 * i];
        size_t idx = (size_t)mat * 65536 + (size_t)(nb + ty + 8 * i) * 256 + kb + tx;
        __nv_bfloat16 h = __float2bfloat16(v);
        th[idx] = h;
        tl[idx] = __float2bfloat16(v - __bfloat162float(h));
    }
}

// ---------------------------------------------------------------------------
// Encoder GEMM (M=64, N=128, 3-stage cp.async, 1 sync/chunk). Round-5 proven.
// relu(C+bias) -> bf16 hi/lo
// ---------------------------------------------------------------------------
#define E_AH 0
#define E_AL 5120
#define E_BH 10240
#define E_BL 20480
#define E_SZ 30720
#define ENC_SMEM (3 * E_SZ)

__global__ __launch_bounds__(256, 2) void enc_kernel(
    const __nv_bfloat16* __restrict__ Ah, const __nv_bfloat16* __restrict__ Al,
    const __nv_bfloat16* __restrict__ Bh, const __nv_bfloat16* __restrict__ Bl,
    const float* __restrict__ bias,
    __nv_bfloat16* __restrict__ oh, __nv_bfloat16* __restrict__ ol)
{
    extern __shared__ char smem[];
    const uint32_t sbase = smem_u32(smem);
    const int tid = threadIdx.x;
    const int lane = tid & 31, warp = tid >> 5;
    const int m0 = blockIdx.x * 64;
    const int n0 = blockIdx.y * 128;
    const int wm = (warp >> 2) * 32;
    const int wn = (warp & 3) * 32;

    float c[2][4][4];
#pragma unroll
    for (int mf = 0; mf < 2; mf++)
#pragma unroll
        for (int nf = 0; nf < 4; nf++)
#pragma unroll
            for (int q = 0; q < 4; q++) c[mf][nf][q] = 0.f;

    const int crow = tid >> 2;
    const int cu   = tid & 3;
    const int arow = (lane & 7) + ((lane >> 3) & 1) * 8;
    const int acol = (lane >> 4) * 8;
    const int brow = (lane & 7) + (lane >> 4) * 8;
    const int bcol = ((lane >> 3) & 1) * 8;

#define E_ISSUE(CI) do {                                                        \
    const int k0_ = (CI) * 32;                                                  \
    const uint32_t st_ = sbase + ((CI) % 3) * E_SZ;                             \
    const uint32_t da = st_ + crow * 80 + cu * 16;                              \
    const size_t ga = (size_t)(m0 + crow) * 256 + k0_ + cu * 8;                 \
    const size_t gb = (size_t)(n0 + crow) * 256 + k0_ + cu * 8;                 \
    CP_ASYNC16(da,         Ah + ga);                                            \
    CP_ASYNC16(da + E_AL,  Al + ga);                                            \
    CP_ASYNC16(st_ + E_BH + crow * 80 + cu * 16,        Bh + gb);               \
    CP_ASYNC16(st_ + E_BH + (crow + 64) * 80 + cu * 16, Bh + gb + 64 * 256);    \
    CP_ASYNC16(st_ + E_BL + crow * 80 + cu * 16,        Bl + gb);               \
    CP_ASYNC16(st_ + E_BL + (crow + 64) * 80 + cu * 16, Bl + gb + 64 * 256);    \
    CP_COMMIT();                                                                \
} while (0)

    E_ISSUE(0);
    E_ISSUE(1);

#pragma unroll 1
    for (int ci = 0; ci < 8; ci++) {
        if (ci < 7) CP_WAIT1(); else CP_WAIT0();
        __syncthreads();
        if (ci < 6) E_ISSUE(ci + 2);

        const uint32_t st = sbase + (ci % 3) * E_SZ;
#pragma unroll
        for (int kk = 0; kk < 32; kk += 16) {
            uint32_t ah[2][4], al[2][4];
#pragma unroll
            for (int mf = 0; mf < 2; mf++) {
                uint32_t addr = st + (wm + mf * 16 + arow) * 80 + (kk + acol) * 2;
                LDSM4(ah[mf], addr);
                LDSM4(al[mf], addr + E_AL);
            }
            uint32_t bhf[4][2], blf[4][2];
#pragma unroll
            for (int np = 0; np < 2; np++) {
                uint32_t addr = st + E_BH
                              + (wn + np * 16 + brow) * 80 + (kk + bcol) * 2;
                uint32_t r[4];
                LDSM4(r, addr);
                bhf[2 * np][0] = r[0]; bhf[2 * np][1] = r[1];
                bhf[2 * np + 1][0] = r[2]; bhf[2 * np + 1][1] = r[3];
                LDSM4(r, addr + (E_BL - E_BH));
                blf[2 * np][0] = r[0]; blf[2 * np][1] = r[1];
                blf[2 * np + 1][0] = r[2]; blf[2 * np + 1][1] = r[3];
            }
#pragma unroll
            for (int mf = 0; mf < 2; mf++)
#pragma unroll
                for (int nf = 0; nf < 4; nf++) {
                    mma_bf16(c[mf][nf], ah[mf], bhf[nf]);
                    mma_bf16(c[mf][nf], ah[mf], blf[nf]);
                    mma_bf16(c[mf][nf], al[mf], bhf[nf]);
                }
        }
    }
#undef E_ISSUE

    const int erow = lane >> 2;
    const int ecol = (lane & 3) * 2;
#pragma unroll
    for (int mf = 0; mf < 2; mf++) {
        const int gr0 = m0 + wm + mf * 16 + erow;
#pragma unroll
        for (int nf = 0; nf < 4; nf++) {
            const int gc = n0 + wn + nf * 8 + ecol;
            float2 bb = *(const float2*)&bias[gc];
            float v00 = fmaxf(c[mf][nf][0] + bb.x, 0.f);
            float v01 = fmaxf(c[mf][nf][1] + bb.y, 0.f);
            float v10 = fmaxf(c[mf][nf][2] + bb.x, 0.f);
            float v11 = fmaxf(c[mf][nf][3] + bb.y, 0.f);
            const size_t i0 = (size_t)gr0 * 256 + gc;
            const size_t i1 = (size_t)(gr0 + 8) * 256 + gc;
            uint32_t h0, l0, h1, l1;
            split2(v00, v01, h0, l0);
            split2(v10, v11, h1, l1);
            *(uint32_t*)(oh + i0) = h0;
            *(uint32_t*)(oh + i1) = h1;
            *(uint32_t*)(ol + i0) = l0;
            *(uint32_t*)(ol + i1) = l1;
        }
    }
}

// ---------------------------------------------------------------------------
// Leaf GEMM (M=128, N=128, 2-stage, round-4 proven shape).
// atomicAdd(yleaf, sum_n relu(C+b1)*W2)
// ---------------------------------------------------------------------------
#define L_TILE 10240                 // 128 rows * 80B
#define L_STAGE (4 * L_TILE)         // Ah, Al, Bh, Bl
#define LEAF_SMEM (2 * L_STAGE + 1024)

__global__ __launch_bounds__(256, 2) void leaf_kernel(
    const __nv_bfloat16* __restrict__ Ah, const __nv_bfloat16* __restrict__ Al,
    const __nv_bfloat16* __restrict__ Bh, const __nv_bfloat16* __restrict__ Bl,
    const float* __restrict__ bias, const float* __restrict__ w2,
    float* __restrict__ yleaf)
{
    extern __shared__ char smem[];
    const uint32_t sbase = smem_u32(smem);
    const int tid = threadIdx.x;
    const int lane = tid & 31, warp = tid >> 5;
    const int m0 = blockIdx.x * 128;
    const int n0 = blockIdx.y * 128;
    const int mat = blockIdx.z;
    const int wm = (warp >> 1) * 32;
    const int wn = (warp & 1) * 64;

    const __nv_bfloat16* bhp = Bh + (size_t)mat * 65536;
    const __nv_bfloat16* blp = Bl + (size_t)mat * 65536;

    float* s_bias = (float*)(smem + 2 * L_STAGE);
    float* s_w2   = (float*)(smem + 2 * L_STAGE + 512);
    if (tid < 128) {
        s_bias[tid] = bias[(size_t)mat * 256 + n0 + tid];
        s_w2[tid]   = w2[(size_t)mat * 256 + n0 + tid];
    }

    float c[2][8][4];
#pragma unroll
    for (int mf = 0; mf < 2; mf++)
#pragma unroll
        for (int nf = 0; nf < 8; nf++)
#pragma unroll
            for (int q = 0; q < 4; q++) c[mf][nf][q] = 0.f;

    const int crow = tid >> 2;
    const int cu   = tid & 3;
    const int arow = (lane & 7) + ((lane >> 3) & 1) * 8;
    const int acol = (lane >> 4) * 8;
    const int brow = (lane & 7) + (lane >> 4) * 8;
    const int bcol = ((lane >> 3) & 1) * 8;

#define L_ISSUE(CI) do {                                                        \
    const int k0_ = (CI) * 32;                                                  \
    const uint32_t st_ = sbase + ((CI) & 1) * L_STAGE;                          \
    const uint32_t d0 = st_ + crow * 80 + cu * 16;                              \
    const uint32_t d1 = st_ + (crow + 64) * 80 + cu * 16;                       \
    const size_t ga = (size_t)(m0 + crow) * 256 + k0_ + cu * 8;                 \
    const size_t gb = (size_t)(n0 + crow) * 256 + k0_ + cu * 8;                 \
    CP_ASYNC16(d0,                  Ah + ga);                                   \
    CP_ASYNC16(d1,                  Ah + ga + 64 * 256);                        \
    CP_ASYNC16(d0 + L_TILE,         Al + ga);                                   \
    CP_ASYNC16(d1 + L_TILE,         Al + ga + 64 * 256);                        \
    CP_ASYNC16(d0 + 2 * L_TILE,     bhp + gb);                                  \
    CP_ASYNC16(d1 + 2 * L_TILE,     bhp + gb + 64 * 256);                       \
    CP_ASYNC16(d0 + 3 * L_TILE,     blp + gb);                                  \
    CP_ASYNC16(d1 + 3 * L_TILE,     blp + gb + 64 * 256);                       \
    CP_COMMIT();                                                                \
} while (0)

    L_ISSUE(0);

#pragma unroll 1
    for (int ci = 0; ci < 8; ci++) {
        if (ci < 7) { L_ISSUE(ci + 1); CP_WAIT1(); }
        else        { CP_WAIT0(); }
        __syncthreads();

        const uint32_t st = sbase + (ci & 1) * L_STAGE;
#pragma unroll
        for (int kk = 0; kk < 32; kk += 16) {
            uint32_t ah[2][4], al[2][4];
#pragma unroll
            for (int mf = 0; mf < 2; mf++) {
                uint32_t addr = st + (wm + mf * 16 + arow) * 80 + (kk + acol) * 2;
                LDSM4(ah[mf], addr);
                LDSM4(al[mf], addr + L_TILE);
            }
            uint32_t bhf[8][2], blf[8][2];
#pragma unroll
            for (int np = 0; np < 4; np++) {
                uint32_t addr = st + 2 * L_TILE
                              + (wn + np * 16 + brow) * 80 + (kk + bcol) * 2;
                uint32_t r[4];
                LDSM4(r, addr);
                bhf[2 * np][0] = r[0]; bhf[2 * np][1] = r[1];
                bhf[2 * np + 1][0] = r[2]; bhf[2 * np + 1][1] = r[3];
                LDSM4(r, addr + L_TILE);
                blf[2 * np][0] = r[0]; blf[2 * np][1] = r[1];
                blf[2 * np + 1][0] = r[2]; blf[2 * np + 1][1] = r[3];
            }
#pragma unroll
            for (int mf = 0; mf < 2; mf++)
#pragma unroll
                for (int nf = 0; nf < 8; nf++) {
                    mma_bf16(c[mf][nf], ah[mf], bhf[nf]);
                    mma_bf16(c[mf][nf], ah[mf], blf[nf]);
                    mma_bf16(c[mf][nf], al[mf], bhf[nf]);
                }
        }
        __syncthreads();
    }
#undef L_ISSUE

    const int erow = lane >> 2;
    const int ecol = (lane & 3) * 2;
    float part[2][2] = {{0.f, 0.f}, {0.f, 0.f}};
#pragma unroll
    for (int mf = 0; mf < 2; mf++)
#pragma unroll
        for (int nf = 0; nf < 8; nf++) {
            const int lc = wn + nf * 8 + ecol;
            const float b0s = s_bias[lc], b1s = s_bias[lc + 1];
            const float w0 = s_w2[lc], w1 = s_w2[lc + 1];
            part[mf][0] = fmaf(fmaxf(c[mf][nf][0] + b0s, 0.f), w0, part[mf][0]);
            part[mf][0] = fmaf(fmaxf(c[mf][nf][1] + b1s, 0.f), w1, part[mf][0]);
            part[mf][1] = fmaf(fmaxf(c[mf][nf][2] + b0s, 0.f), w0, part[mf][1]);
            part[mf][1] = fmaf(fmaxf(c[mf][nf][3] + b1s, 0.f), w1, part[mf][1]);
        }
#pragma unroll
    for (int mf = 0; mf < 2; mf++)
#pragma unroll
        for (int h = 0; h < 2; h++) {
            part[mf][h] += __shfl_xor_sync(0xffffffffu, part[mf][h], 1);
            part[mf][h] += __shfl_xor_sync(0xffffffffu, part[mf][h], 2);
        }
    if ((lane & 3) == 0) {
#pragma unroll
        for (int mf = 0; mf < 2; mf++)
#pragma unroll
            for (int h = 0; h < 2; h++) {
                const int row = m0 + wm + mf * 16 + h * 8 + erow;
                atomicAdd(&yleaf[(size_t)mat * BATCH + row], part[mf][h]);
            }
    }
}

// ---------------------------------------------------------------------------
// Inner-node kernel (round-5 proven): Phase A mma (3-stage), Phase B mma with
// Ww streamed from L2 (3-stage), fused softmax epilogue.
// ---------------------------------------------------------------------------
#define IA_SZ  20480
#define IB_SZ  24576
#define IN_HH  73728
#define IN_HL  82944
#define IN_RED 92160
#define IN_WBS 93696
#define IN_WBTS 93952
#define IN_SMEM 94208

__global__ __launch_bounds__(256, 2) void inner_mma_kernel(
    const __nv_bfloat16* __restrict__ eh, const __nv_bfloat16* __restrict__ el,
    const __nv_bfloat16* __restrict__ w1h, const __nv_bfloat16* __restrict__ w1l,
    const __nv_bfloat16* __restrict__ wwh, const __nv_bfloat16* __restrict__ wwl,
    const float* __restrict__ x, const float* __restrict__ b1,
    const float* __restrict__ bw, const float* __restrict__ Wb,
    const float* __restrict__ bb, const float* __restrict__ Wbt,
    const float* __restrict__ bbt, float* __restrict__ pR)
{
    extern __shared__ char smem[];
    const uint32_t sb = smem_u32(smem);
    const int tid = threadIdx.x, lane = tid & 31, w = tid >> 5;
    const int n = blockIdx.y, m0 = blockIdx.x * 64;

    float* sWb  = (float*)(smem + IN_WBS);
    float* sWbt = (float*)(smem + IN_WBTS);
    if (tid < HDIM)                sWb[tid] = Wb[n * HDIM + tid];
    else if (tid < 2 * HDIM)       sWbt[tid - HDIM] = Wbt[n * HDIM + tid - HDIM];

    const int crow = tid >> 2, cu = tid & 3;
    const __nv_bfloat16* w1hp = w1h + (size_t)n * 64 * 256;
    const __nv_bfloat16* w1lp = w1l + (size_t)n * 64 * 256;
    const __nv_bfloat16* wwhp = wwh + (size_t)n * 256 * 64;
    const __nv_bfloat16* wwlp = wwl + (size_t)n * 256 * 64;

#define IN_ISSUE(CI) do {                                           \
    const int k0_ = (CI) * 32;                                      \
    const uint32_t st_ = sb + ((CI) % 3) * IA_SZ;                   \
    const uint32_t d = st_ + crow * 80 + cu * 16;                   \
    const size_t ga = (size_t)(m0 + crow) * 256 + k0_ + cu * 8;     \
    const size_t gw = (size_t)crow * 256 + k0_ + cu * 8;            \
    CP_ASYNC16(d,         eh + ga);                                 \
    CP_ASYNC16(d + 5120,  el + ga);                                 \
    CP_ASYNC16(d + 10240, w1hp + gw);                               \
    CP_ASYNC16(d + 15360, w1lp + gw);                               \
    CP_COMMIT();                                                    \
} while (0)

    const int arow = (lane & 7) + ((lane >> 3) & 1) * 8;
    const int acol = (lane >> 4) * 8;
    const int brow = (lane & 7) + (lane >> 4) * 8;
    const int bcol = ((lane >> 3) & 1) * 8;

    // ---- Phase A ----
    const int wmA = (w >> 1) * 16, wnA = (w & 1) * 32;
    float accA[4][4];
#pragma unroll
    for (int i = 0; i < 4; i++)
#pragma unroll
        for (int q = 0; q < 4; q++) accA[i][q] = 0.f;

    IN_ISSUE(0);
    IN_ISSUE(1);

#pragma unroll 1
    for (int ci = 0; ci < 8; ci++) {
        if (ci < 7) CP_WAIT1(); else CP_WAIT0();
        __syncthreads();
        if (ci < 6) IN_ISSUE(ci + 2);

        const uint32_t st = sb + (ci % 3) * IA_SZ;
#pragma unroll
        for (int kk = 0; kk < 32; kk += 16) {
            uint32_t ah[4], al[4];
            const uint32_t aaddr = st + (wmA + arow) * 80 + (kk + acol) * 2;
            LDSM4(ah, aaddr);
            LDSM4(al, aaddr + 5120);
            uint32_t bh[4][2], bl[4][2];
#pragma unroll
            for (int g = 0; g < 2; g++) {
                const uint32_t baddr = st + 10240
                    + (wnA + g * 16 + brow) * 80 + (kk + bcol) * 2;
                uint32_t r[4];
                LDSM4(r, baddr);
                bh[2 * g][0] = r[0]; bh[2 * g][1] = r[1];
                bh[2 * g + 1][0] = r[2]; bh[2 * g + 1][1] = r[3];
                LDSM4(r, baddr + 5120);
                bl[2 * g][0] = r[0]; bl[2 * g][1] = r[1];
                bl[2 * g + 1][0] = r[2]; bl[2 * g + 1][1] = r[3];
            }
#pragma unroll
            for (int nf = 0; nf < 4; nf++) {
                mma_bf16(accA[nf], ah, bh[nf]);
                mma_bf16(accA[nf], ah, bl[nf]);
                mma_bf16(accA[nf], al, bh[nf]);
            }
        }
    }
#undef IN_ISSUE

    // Phase A epilogue
    {
        const int r0 = wmA + (lane >> 2);
#pragma unroll
        for (int nf = 0; nf < 4; nf++) {
            const int col = wnA + nf * 8 + (lane & 3) * 2;
            const float bb0 = (col < HDIM)     ? b1[n * HDIM + col]     : 0.f;
            const float bb1 = (col + 1 < HDIM) ? b1[n * HDIM + col + 1] : 0.f;
            float v00 = fmaxf(accA[nf][0] + bb0, 0.f);
            float v01 = fmaxf(accA[nf][1] + bb1, 0.f);
            float v10 = fmaxf(accA[nf][2] + bb0, 0.f);
            float v11 = fmaxf(accA[nf][3] + bb1, 0.f);
            uint32_t h0, l0, h1, l1;
            split2(v00, v01, h0, l0);
            split2(v10, v11, h1, l1);
            *(uint32_t*)(smem + IN_HH + r0 * 144 + col * 2) = h0;
            *(uint32_t*)(smem + IN_HL + r0 * 144 + col * 2) = l0;
            *(uint32_t*)(smem + IN_HH + (r0 + 8) * 144 + col * 2) = h1;
            *(uint32_t*)(smem + IN_HL + (r0 + 8) * 144 + col * 2) = l1;
        }
    }
    __syncthreads();

    // ---- Phase B ----
#define IN_ISSUE_B(KK) do {                                         \
    const uint32_t st_ = sb + ((KK) % 3) * IB_SZ;                   \
    const uint32_t d = st_ + tid * 48;                              \
    const size_t g = (size_t)tid * 64 + (KK) * 16;                  \
    CP_ASYNC16(d,          wwhp + g);                               \
    CP_ASYNC16(d + 16,     wwhp + g + 8);                           \
    CP_ASYNC16(d + 12288,      wwlp + g);                           \
    CP_ASYNC16(d + 12288 + 16, wwlp + g + 8);                       \
    CP_COMMIT();                                                    \
} while (0)

    const int wmB = (w >> 1) * 16, wnB = (w & 1) * 128;
    float z[16][4];
#pragma unroll
    for (int nf = 0; nf < 16; nf++)
#pragma unroll
        for (int q = 0; q < 4; q++) z[nf][q] = 0.f;

    IN_ISSUE_B(0);
    IN_ISSUE_B(1);

#pragma unroll 1
    for (int kk = 0; kk < 4; kk++) {
        if (kk < 3) CP_WAIT1(); else CP_WAIT0();
        __syncthreads();
        if (kk < 2) IN_ISSUE_B(kk + 2);

        const uint32_t st = sb + (kk % 3) * IB_SZ;
        uint32_t ah[4], al[4];
        const uint32_t aaddr = sb + IN_HH + (wmB + arow) * 144 + (kk * 16 + acol) * 2;
        LDSM4(ah, aaddr);
        LDSM4(al, aaddr + (IN_HL - IN_HH));
#pragma unroll
        for (int g = 0; g < 8; g++) {
            const uint32_t baddr = st + (wnB + g * 16 + brow) * 48 + bcol * 2;
            uint32_t rh[4], rl[4];
            LDSM4(rh, baddr);
            LDSM4(rl, baddr + 12288);
            uint32_t b0h[2] = {rh[0], rh[1]}, b1h[2] = {rh[2], rh[3]};
            uint32_t b0l[2] = {rl[0], rl[1]}, b1l[2] = {rl[2], rl[3]};
            mma_bf16(z[2 * g],     ah, b0h);
            mma_bf16(z[2 * g],     ah, b0l);
            mma_bf16(z[2 * g],     al, b0h);
            mma_bf16(z[2 * g + 1], ah, b1h);
            mma_bf16(z[2 * g + 1], ah, b1l);
            mma_bf16(z[2 * g + 1], al, b1h);
        }
    }
#undef IN_ISSUE_B

    // ---- Phase B epilogue ----
    float* redmax = (float*)(smem + IN_RED);
    float* redse  = redmax + 128;
    float* redsx  = redse + 128;

    const int r0 = wmB + (lane >> 2), r1 = r0 + 8;
    float mx0 = -1e30f, mx1 = -1e30f;
#pragma unroll
    for (int nf = 0; nf < 16; nf++) {
        const int col = wnB + nf * 8 + (lane & 3) * 2;
        float2 bwv = *(const float2*)&bw[n * 256 + col];
        z[nf][0] += bwv.x; z[nf][1] += bwv.y;
        z[nf][2] += bwv.x; z[nf][3] += bwv.y;
        mx0 = fmaxf(mx0, fmaxf(z[nf][0], z[nf][1]));
        mx1 = fmaxf(mx1, fmaxf(z[nf][2], z[nf][3]));
    }
    mx0 = fmaxf(mx0, __shfl_xor_sync(0xffffffffu, mx0, 1));
    mx0 = fmaxf(mx0, __shfl_xor_sync(0xffffffffu, mx0, 2));
    mx1 = fmaxf(mx1, __shfl_xor_sync(0xffffffffu, mx1, 1));
    mx1 = fmaxf(mx1, __shfl_xor_sync(0xffffffffu, mx1, 2));
    if ((lane & 3) == 0) {
        redmax[(w & 1) * 64 + r0] = mx0;
        redmax[(w & 1) * 64 + r1] = mx1;
    }
    __syncthreads();
    mx0 = fmaxf(redmax[r0], redmax[64 + r0]);
    mx1 = fmaxf(redmax[r1], redmax[64 + r1]);

    float se0 = 0.f, sx0 = 0.f, se1 = 0.f, sx1 = 0.f;
    const float* x0 = x + (size_t)(m0 + r0) * 256;
    const float* x1 = x + (size_t)(m0 + r1) * 256;
#pragma unroll
    for (int nf = 0; nf < 16; nf++) {
        const int col = wnB + nf * 8 + (lane & 3) * 2;
        float2 xv0 = *(const float2*)&x0[col];
        float2 xv1 = *(const float2*)&x1[col];
        float e;
        e = __expf(z[nf][0] - mx0); se0 += e; sx0 = fmaf(e, xv0.x, sx0);
        e = __expf(z[nf][1] - mx0); se0 += e; sx0 = fmaf(e, xv0.y, sx0);
        e = __expf(z[nf][2] - mx1); se1 += e; sx1 = fmaf(e, xv1.x, sx1);
        e = __expf(z[nf][3] - mx1); se1 += e; sx1 = fmaf(e, xv1.y, sx1);
    }
#pragma unroll
    for (int off = 1; off <= 2; off <<= 1) {
        se0 += __shfl_xor_sync(0xffffffffu, se0, off);
        sx0 += __shfl_xor_sync(0xffffffffu, sx0, off);
        se1 += __shfl_xor_sync(0xffffffffu, se1, off);
        sx1 += __shfl_xor_sync(0xffffffffu, sx1, off);
    }
    if ((lane & 3) == 0) {
        redse[(w & 1) * 64 + r0] = se0; redse[(w & 1) * 64 + r1] = se1;
        redsx[(w & 1) * 64 + r0] = sx0; redsx[(w & 1) * 64 + r1] = sx1;
    }
    __syncthreads();

    if ((w & 1) == 0) {
        float pb0 = 0.f, pbt0 = 0.f, pb1 = 0.f, pbt1 = 0.f;
        for (int j = (lane & 3); j < HDIM; j += 4) {
            float h0 = __bfloat162float(*(const __nv_bfloat16*)(smem + IN_HH + r0 * 144 + j * 2))
                     + __bfloat162float(*(const __nv_bfloat16*)(smem + IN_HL + r0 * 144 + j * 2));
            float h1 = __bfloat162float(*(const __nv_bfloat16*)(smem + IN_HH + r1 * 144 + j * 2))
                     + __bfloat162float(*(const __nv_bfloat16*)(smem + IN_HL + r1 * 144 + j * 2));
            pb0  = fmaf(h0, sWb[j],  pb0);
            pbt0 = fmaf(h0, sWbt[j], pbt0);
            pb1  = fmaf(h1, sWb[j],  pb1);
            pbt1 = fmaf(h1, sWbt[j], pbt1);
        }
#pragma unroll
        for (int off = 1; off <= 2; off <<= 1) {
            pb0  += __shfl_xor_sync(0xffffffffu, pb0, off);
            pbt0 += __shfl_xor_sync(0xffffffffu, pbt0, off);
            pb1  += __shfl_xor_sync(0xffffffffu, pb1, off);
            pbt1 += __shfl_xor_sync(0xffffffffu, pbt1, off);
        }
        if ((lane & 3) == 0) {
            const float bbn = bb[n], bbtn = bbt[n];
            float seA = redse[r0] + redse[64 + r0];
            float sxA = redsx[r0] + redsx[64 + r0];
            float val = (pbt0 + bbtn) * (sxA / seA + pb0 + bbn);
            pR[(size_t)n * BATCH + m0 + r0] = 1.f / (1.f + __expf(-val));
            seA = redse[r1] + redse[64 + r1];
            sxA = redsx[r1] + redsx[64 + r1];
            val = (pbt1 + bbtn) * (sxA / seA + pb1 + bbn);
            pR[(size_t)n * BATCH + m0 + r1] = 1.f / (1.f + __expf(-val));
        }
    }
}

// ---------------------------------------------------------------------------
// Combine
// ---------------------------------------------------------------------------
__global__ __launch_bounds__(256) void combine_kernel(
    const float* __restrict__ pR, const float* __restrict__ yl,
    const float* __restrict__ b2, float* __restrict__ out)
{
    const int b = blockIdx.x * 256 + threadIdx.x;
    float p[N_INNER];
#pragma unroll
    for (int i = 0; i < N_INNER; i++) p[i] = pR[(size_t)i * BATCH + b];

    float prob[N_LEAF];
    prob[0] = 1.f;
#pragma unroll
    for (int lev = 0; lev < 5; lev++) {
        const int cnt = 1 << lev;
        const int off = cnt - 1;
#pragma unroll
        for (int i = N_LEAF - 1; i >= 0; i--) {
            if (i < cnt) {
                float pr   = p[off + i];
                float base = prob[i];
                prob[2 * i]     = base * (1.f - pr);
                prob[2 * i + 1] = base * pr;
            }
        }
    }
    float acc = 0.f;
#pragma unroll
    for (int l = 0; l < N_LEAF; l++)
        acc = fmaf(prob[l], yl[(size_t)l * BATCH + b] + b2[l], acc);
    out[b] = acc;
}

// ---------------------------------------------------------------------------
extern "C" void kernel_launch(void* const* d_in, const int* in_sizes, int n_in,
                              void* d_out, int out_size)
{
    const float* x       = (const float*)d_in[0];
    const float* enc_W   = (const float*)d_in[1];
    const float* enc_b   = (const float*)d_in[2];
    const float* in_W1   = (const float*)d_in[3];
    const float* in_b1   = (const float*)d_in[4];
    const float* in_Ww   = (const float*)d_in[5];
    const float* in_bw   = (const float*)d_in[6];
    const float* in_Wb   = (const float*)d_in[7];
    const float* in_bb   = (const float*)d_in[8];
    const float* in_Wbt  = (const float*)d_in[9];
    const float* in_bbt  = (const float*)d_in[10];
    const float* lf_W1   = (const float*)d_in[11];
    const float* lf_b1   = (const float*)d_in[12];
    const float* lf_W2   = (const float*)d_in[13];
    const float* lf_b2   = (const float*)d_in[14];
    float* out = (float*)d_out;

    float *pR, *yl;
    __nv_bfloat16 *xh, *xl, *e0h, *e0l, *e1h, *e1l, *wth, *wtl;
    __nv_bfloat16 *w1th, *w1tl, *wwth, *wwtl;
    cudaGetSymbolAddress((void**)&pR,  g_pR);
    cudaGetSymbolAddress((void**)&yl,  g_yleaf);
    cudaGetSymbolAddress((void**)&xh,  g_xh);
    cudaGetSymbolAddress((void**)&xl,  g_xl);
    cudaGetSymbolAddress((void**)&e0h, g_e0h);
    cudaGetSymbolAddress((void**)&e0l, g_e0l);
    cudaGetSymbolAddress((void**)&e1h, g_e1h);
    cudaGetSymbolAddress((void**)&e1l, g_e1l);
    cudaGetSymbolAddress((void**)&wth, g_wth);
    cudaGetSymbolAddress((void**)&wtl, g_wtl);
    cudaGetSymbolAddress((void**)&w1th, g_w1th);
    cudaGetSymbolAddress((void**)&w1tl, g_w1tl);
    cudaGetSymbolAddress((void**)&wwth, g_wwth);
    cudaGetSymbolAddress((void**)&wwtl, g_wwtl);

    cudaFuncSetAttribute(enc_kernel,  cudaFuncAttributeMaxDynamicSharedMemorySize, ENC_SMEM);
    cudaFuncSetAttribute(leaf_kernel, cudaFuncAttributeMaxDynamicSharedMemorySize, LEAF_SMEM);
    cudaFuncSetAttribute(inner_mma_kernel, cudaFuncAttributeMaxDynamicSharedMemorySize, IN_SMEM);

    // --- prep ---
    prep_small_kernel<<<PS_Z, 256>>>(x, xh, xl, in_W1, w1th, w1tl,
                                     in_Ww, wwth, wwtl, yl);
    prep_w_kernel<<<dim3(8, 8, 4),  dim3(32, 8)>>>(enc_W, wth, wtl);
    prep_w_kernel<<<dim3(8, 8, 32), dim3(32, 8)>>>(lf_W1, wth + 4 * 65536, wtl + 4 * 65536);

    // --- encoder: 4 layers (M=64 x N=128 tiles, grid 256) ---
    enc_kernel<<<dim3(128, 2), 256, ENC_SMEM>>>(xh, xl, wth, wtl,
        enc_b, e0h, e0l);
    enc_kernel<<<dim3(128, 2), 256, ENC_SMEM>>>(e0h, e0l, wth + 65536, wtl + 65536,
        enc_b + 256, e1h, e1l);
    enc_kernel<<<dim3(128, 2), 256, ENC_SMEM>>>(e1h, e1l, wth + 2 * 65536, wtl + 2 * 65536,
        enc_b + 512, e0h, e0l);
    enc_kernel<<<dim3(128, 2), 256, ENC_SMEM>>>(e0h, e0l, wth + 3 * 65536, wtl + 3 * 65536,
        enc_b + 768, e1h, e1l);

    // --- inner gates ---
    inner_mma_kernel<<<dim3(BATCH / 64, N_INNER), 256, IN_SMEM>>>(
        e1h, e1l, w1th, w1tl, wwth, wwtl,
        x, in_b1, in_bw, in_Wb, in_bb, in_Wbt, in_bbt, pR);

    // --- leaves (M=128 tiles, grid 64x2x32) ---
    leaf_kernel<<<dim3(64, 2, N_LEAF), 256, LEAF_SMEM>>>(
        e1h, e1l, wth + 4 * 65536, wtl + 4 * 65536,
        lf_b1, lf_W2, yl);

    // --- combine ---
    combine_kernel<<<BATCH / 256, 256>>>(pR, yl, lf_b2, out);
}

// round 7
// speedup vs baseline: 1.1007x; 1.0127x over previous
#include <cuda_runtime.h>
#include <cuda_bf16.h>
#include <cstdint>
#include <math.h>

#define BATCH 8192
#define EDIM  256
#define HDIM  50
#define N_INNER 31
#define N_LEAF  32

// ---------------------------------------------------------------------------
// Device scratch
// ---------------------------------------------------------------------------
__device__ float g_pR[N_INNER * BATCH];
__device__ float g_yleaf[N_LEAF * BATCH];

__device__ __nv_bfloat16 g_xh[BATCH * EDIM];
__device__ __nv_bfloat16 g_xl[BATCH * EDIM];
__device__ __nv_bfloat16 g_e0h[BATCH * EDIM];
__device__ __nv_bfloat16 g_e0l[BATCH * EDIM];
__device__ __nv_bfloat16 g_e1h[BATCH * EDIM];
__device__ __nv_bfloat16 g_e1l[BATCH * EDIM];
// transposed weights: 0..3 encoder, 4..35 leaves. layout [mat][N=256][K=256]
__device__ __nv_bfloat16 g_wth[36 * 65536];
__device__ __nv_bfloat16 g_wtl[36 * 65536];
// inner: W1 transposed [31][64][256] (rows 50..63 zero)
__device__ __nv_bfloat16 g_w1th[N_INNER * 64 * 256];
__device__ __nv_bfloat16 g_w1tl[N_INNER * 64 * 256];
// inner: Ww transposed [31][256][64] (cols 50..63 zero)
__device__ __nv_bfloat16 g_wwth[N_INNER * 256 * 64];
__device__ __nv_bfloat16 g_wwtl[N_INNER * 256 * 64];

// ---------------------------------------------------------------------------
// Helpers
// ---------------------------------------------------------------------------
__device__ __forceinline__ uint32_t smem_u32(const void* p) {
    uint32_t a;
    asm("{ .reg .u64 t; cvta.to.shared.u64 t, %1; cvt.u32.u64 %0, t; }" : "=r"(a) : "l"(p));
    return a;
}
#define CP_ASYNC16(dst, src) \
    asm volatile("cp.async.cg.shared.global [%0], [%1], 16;" :: "r"(dst), "l"(src) : "memory")
#define CP_COMMIT() asm volatile("cp.async.commit_group;" ::: "memory")
#define CP_WAIT1()  asm volatile("cp.async.wait_group 1;" ::: "memory")
#define CP_WAIT0()  asm volatile("cp.async.wait_group 0;" ::: "memory")

#define LDSM4(r, addr) \
    asm volatile("ldmatrix.sync.aligned.m8n8.x4.shared.b16 {%0,%1,%2,%3}, [%4];" \
        : "=r"((r)[0]), "=r"((r)[1]), "=r"((r)[2]), "=r"((r)[3]) : "r"(addr))

__device__ __forceinline__ void mma_bf16(float* c, const uint32_t* a, const uint32_t* b) {
    asm volatile(
        "mma.sync.aligned.m16n8k16.row.col.f32.bf16.bf16.f32 "
        "{%0,%1,%2,%3}, {%4,%5,%6,%7}, {%8,%9}, {%0,%1,%2,%3};"
        : "+f"(c[0]), "+f"(c[1]), "+f"(c[2]), "+f"(c[3])
        : "r"(a[0]), "r"(a[1]), "r"(a[2]), "r"(a[3]), "r"(b[0]), "r"(b[1]));
}

__device__ __forceinline__ void split2(float a, float b, uint32_t& hi, uint32_t& lo) {
    __nv_bfloat16 h0 = __float2bfloat16(a), h1 = __float2bfloat16(b);
    __nv_bfloat16 l0 = __float2bfloat16(a - __bfloat162float(h0));
    __nv_bfloat16 l1 = __float2bfloat16(b - __bfloat162float(h1));
    __nv_bfloat16 hh[2] = {h0, h1}, ll[2] = {l0, l1};
    hi = *(uint32_t*)hh;
    lo = *(uint32_t*)ll;
}

// ---------------------------------------------------------------------------
// One mega-prep kernel. Regions by blockIdx.x:
//  R0 x split | R1 W1 t+split | R2 Ww t+split | R3 zero yl | R4 36x W transp.
// ---------------------------------------------------------------------------
#define PR_X   2048
#define PR_W1  (PR_X + 1984)
#define PR_WW  (PR_W1 + 1984)
#define PR_Z   (PR_WW + 256)
#define PR_WT  (PR_Z + 36 * 64)

__global__ __launch_bounds__(256) void prep_all_kernel(
    const float* __restrict__ x, __nv_bfloat16* __restrict__ xh,
    __nv_bfloat16* __restrict__ xl,
    const float* __restrict__ W1, __nv_bfloat16* __restrict__ w1h,
    __nv_bfloat16* __restrict__ w1l,
    const float* __restrict__ Ww, __nv_bfloat16* __restrict__ wwh,
    __nv_bfloat16* __restrict__ wwl,
    float* __restrict__ yl,
    const float* __restrict__ encW, const float* __restrict__ lfW,
    __nv_bfloat16* __restrict__ wth, __nv_bfloat16* __restrict__ wtl)
{
    const int bid = blockIdx.x;
    const int t = threadIdx.x;
    if (bid < PR_X) {
        int i = bid * 256 + t;
        float4 v = ((const float4*)x)[i];
        float f[4] = {v.x, v.y, v.z, v.w};
        __nv_bfloat16 h[4], l[4];
#pragma unroll
        for (int j = 0; j < 4; j++) {
            h[j] = __float2bfloat16(f[j]);
            l[j] = __float2bfloat16(f[j] - __bfloat162float(h[j]));
        }
        *(uint2*)(xh + 4 * (size_t)i) = *(uint2*)h;
        *(uint2*)(xl + 4 * (size_t)i) = *(uint2*)l;
    } else if (bid < PR_W1) {
        int idx = (bid - PR_X) * 256 + t;
        int k = idx & 255, j = (idx >> 8) & 63, n = idx >> 14;
        float v = (j < HDIM) ? W1[((size_t)n * 256 + k) * HDIM + j] : 0.f;
        __nv_bfloat16 h = __float2bfloat16(v);
        w1h[idx] = h;
        w1l[idx] = __float2bfloat16(v - __bfloat162float(h));
    } else if (bid < PR_WW) {
        int idx = (bid - PR_W1) * 256 + t;
        int j = idx & 63, d = (idx >> 6) & 255, n = idx >> 14;
        float v = (j < HDIM) ? Ww[((size_t)n * HDIM + j) * 256 + d] : 0.f;
        __nv_bfloat16 h = __float2bfloat16(v);
        wwh[idx] = h;
        wwl[idx] = __float2bfloat16(v - __bfloat162float(h));
    } else if (bid < PR_Z) {
        int i = (bid - PR_WW) * 256 + t;
        ((float4*)yl)[i] = make_float4(0.f, 0.f, 0.f, 0.f);
    } else {
        // weight transpose: [K][N] f32 -> [N][K] bf16 hi/lo
        __shared__ float tt[32][33];
        const int rel = bid - PR_Z;
        const int mat = rel >> 6;
        const int sub = rel & 63;
        const int nb = (sub & 7) * 32, kb = (sub >> 3) * 32;
        const int tx = t & 31, ty = t >> 5;
        const float* src = (mat < 4) ? (encW + (size_t)mat * 65536)
                                     : (lfW + (size_t)(mat - 4) * 65536);
#pragma unroll
        for (int i = 0; i < 4; i++)
            tt[ty + 8 * i][tx] = src[(size_t)(kb + ty + 8 * i) * 256 + nb + tx];
        __syncthreads();
#pragma unroll
        for (int i = 0; i < 4; i++) {
            float v = tt[tx][ty + 8 * i];
            size_t idx = (size_t)mat * 65536 + (size_t)(nb + ty + 8 * i) * 256 + kb + tx;
            __nv_bfloat16 h = __float2bfloat16(v);
            wth[idx] = h;
            wtl[idx] = __float2bfloat16(v - __bfloat162float(h));
        }
    }
}

// ---------------------------------------------------------------------------
// Encoder GEMM (M=64, N=128, 3-stage cp.async, 1 sync/chunk). Proven r5/r6.
// ---------------------------------------------------------------------------
#define E_AH 0
#define E_AL 5120
#define E_BH 10240
#define E_BL 20480
#define E_SZ 30720
#define ENC_SMEM (3 * E_SZ)

__global__ __launch_bounds__(256, 2) void enc_kernel(
    const __nv_bfloat16* __restrict__ Ah, const __nv_bfloat16* __restrict__ Al,
    const __nv_bfloat16* __restrict__ Bh, const __nv_bfloat16* __restrict__ Bl,
    const float* __restrict__ bias,
    __nv_bfloat16* __restrict__ oh, __nv_bfloat16* __restrict__ ol)
{
    extern __shared__ char smem[];
    const uint32_t sbase = smem_u32(smem);
    const int tid = threadIdx.x;
    const int lane = tid & 31, warp = tid >> 5;
    const int m0 = blockIdx.x * 64;
    const int n0 = blockIdx.y * 128;
    const int wm = (warp >> 2) * 32;
    const int wn = (warp & 3) * 32;

    float c[2][4][4];
#pragma unroll
    for (int mf = 0; mf < 2; mf++)
#pragma unroll
        for (int nf = 0; nf < 4; nf++)
#pragma unroll
            for (int q = 0; q < 4; q++) c[mf][nf][q] = 0.f;

    const int crow = tid >> 2;
    const int cu   = tid & 3;
    const int arow = (lane & 7) + ((lane >> 3) & 1) * 8;
    const int acol = (lane >> 4) * 8;
    const int brow = (lane & 7) + (lane >> 4) * 8;
    const int bcol = ((lane >> 3) & 1) * 8;

#define E_ISSUE(CI) do {                                                        \
    const int k0_ = (CI) * 32;                                                  \
    const uint32_t st_ = sbase + ((CI) % 3) * E_SZ;                             \
    const uint32_t da = st_ + crow * 80 + cu * 16;                              \
    const size_t ga = (size_t)(m0 + crow) * 256 + k0_ + cu * 8;                 \
    const size_t gb = (size_t)(n0 + crow) * 256 + k0_ + cu * 8;                 \
    CP_ASYNC16(da,         Ah + ga);                                            \
    CP_ASYNC16(da + E_AL,  Al + ga);                                            \
    CP_ASYNC16(st_ + E_BH + crow * 80 + cu * 16,        Bh + gb);               \
    CP_ASYNC16(st_ + E_BH + (crow + 64) * 80 + cu * 16, Bh + gb + 64 * 256);    \
    CP_ASYNC16(st_ + E_BL + crow * 80 + cu * 16,        Bl + gb);               \
    CP_ASYNC16(st_ + E_BL + (crow + 64) * 80 + cu * 16, Bl + gb + 64 * 256);    \
    CP_COMMIT();                                                                \
} while (0)

    E_ISSUE(0);
    E_ISSUE(1);

#pragma unroll 1
    for (int ci = 0; ci < 8; ci++) {
        if (ci < 7) CP_WAIT1(); else CP_WAIT0();
        __syncthreads();
        if (ci < 6) E_ISSUE(ci + 2);

        const uint32_t st = sbase + (ci % 3) * E_SZ;
#pragma unroll
        for (int kk = 0; kk < 32; kk += 16) {
            uint32_t ah[2][4], al[2][4];
#pragma unroll
            for (int mf = 0; mf < 2; mf++) {
                uint32_t addr = st + (wm + mf * 16 + arow) * 80 + (kk + acol) * 2;
                LDSM4(ah[mf], addr);
                LDSM4(al[mf], addr + E_AL);
            }
            uint32_t bhf[4][2], blf[4][2];
#pragma unroll
            for (int np = 0; np < 2; np++) {
                uint32_t addr = st + E_BH
                              + (wn + np * 16 + brow) * 80 + (kk + bcol) * 2;
                uint32_t r[4];
                LDSM4(r, addr);
                bhf[2 * np][0] = r[0]; bhf[2 * np][1] = r[1];
                bhf[2 * np + 1][0] = r[2]; bhf[2 * np + 1][1] = r[3];
                LDSM4(r, addr + (E_BL - E_BH));
                blf[2 * np][0] = r[0]; blf[2 * np][1] = r[1];
                blf[2 * np + 1][0] = r[2]; blf[2 * np + 1][1] = r[3];
            }
#pragma unroll
            for (int mf = 0; mf < 2; mf++)
#pragma unroll
                for (int nf = 0; nf < 4; nf++) {
                    mma_bf16(c[mf][nf], ah[mf], bhf[nf]);
                    mma_bf16(c[mf][nf], ah[mf], blf[nf]);
                    mma_bf16(c[mf][nf], al[mf], bhf[nf]);
                }
        }
    }
#undef E_ISSUE

    const int erow = lane >> 2;
    const int ecol = (lane & 3) * 2;
#pragma unroll
    for (int mf = 0; mf < 2; mf++) {
        const int gr0 = m0 + wm + mf * 16 + erow;
#pragma unroll
        for (int nf = 0; nf < 4; nf++) {
            const int gc = n0 + wn + nf * 8 + ecol;
            float2 bb = *(const float2*)&bias[gc];
            float v00 = fmaxf(c[mf][nf][0] + bb.x, 0.f);
            float v01 = fmaxf(c[mf][nf][1] + bb.y, 0.f);
            float v10 = fmaxf(c[mf][nf][2] + bb.x, 0.f);
            float v11 = fmaxf(c[mf][nf][3] + bb.y, 0.f);
            const size_t i0 = (size_t)gr0 * 256 + gc;
            const size_t i1 = (size_t)(gr0 + 8) * 256 + gc;
            uint32_t h0, l0, h1, l1;
            split2(v00, v01, h0, l0);
            split2(v10, v11, h1, l1);
            *(uint32_t*)(oh + i0) = h0;
            *(uint32_t*)(oh + i1) = h1;
            *(uint32_t*)(ol + i0) = l0;
            *(uint32_t*)(ol + i1) = l1;
        }
    }
}

// ---------------------------------------------------------------------------
// TAIL kernel: merged inner (blockIdx.x < 31) + leaf (blockIdx.x >= 31).
// grid (63, 128), block 256. Both paths as in round 6 (proven).
// ---------------------------------------------------------------------------
// leaf layout
#define L_TILE 10240
#define L_STAGE (4 * L_TILE)
// inner layout
#define IA_SZ  20480
#define IB_SZ  24576
#define IN_HH  73728
#define IN_HL  82944
#define IN_RED 92160
#define IN_WBS 93696
#define IN_WBTS 93952
#define TAIL_SMEM 94208

__global__ __launch_bounds__(256, 2) void tail_kernel(
    const __nv_bfloat16* __restrict__ eh, const __nv_bfloat16* __restrict__ el,
    // inner params
    const __nv_bfloat16* __restrict__ w1h, const __nv_bfloat16* __restrict__ w1l,
    const __nv_bfloat16* __restrict__ wwh, const __nv_bfloat16* __restrict__ wwl,
    const float* __restrict__ x, const float* __restrict__ b1,
    const float* __restrict__ bw, const float* __restrict__ Wb,
    const float* __restrict__ bb, const float* __restrict__ Wbt,
    const float* __restrict__ bbt, float* __restrict__ pR,
    // leaf params
    const __nv_bfloat16* __restrict__ Bh, const __nv_bfloat16* __restrict__ Bl,
    const float* __restrict__ lbias, const float* __restrict__ w2,
    float* __restrict__ yleaf)
{
    extern __shared__ char smem[];
    const uint32_t sb = smem_u32(smem);
    const int tid = threadIdx.x, lane = tid & 31, w = tid >> 5;

    const int arow = (lane & 7) + ((lane >> 3) & 1) * 8;
    const int acol = (lane >> 4) * 8;
    const int brow = (lane & 7) + (lane >> 4) * 8;
    const int bcol = ((lane >> 3) & 1) * 8;
    const int crow = tid >> 2, cu = tid & 3;

    if (blockIdx.x < N_INNER) {
        // ================= INNER path =================
        const int n = blockIdx.x, m0 = blockIdx.y * 64;

        float* sWb  = (float*)(smem + IN_WBS);
        float* sWbt = (float*)(smem + IN_WBTS);
        if (tid < HDIM)          sWb[tid] = Wb[n * HDIM + tid];
        else if (tid < 2 * HDIM) sWbt[tid - HDIM] = Wbt[n * HDIM + tid - HDIM];

        const __nv_bfloat16* w1hp = w1h + (size_t)n * 64 * 256;
        const __nv_bfloat16* w1lp = w1l + (size_t)n * 64 * 256;
        const __nv_bfloat16* wwhp = wwh + (size_t)n * 256 * 64;
        const __nv_bfloat16* wwlp = wwl + (size_t)n * 256 * 64;

#define IN_ISSUE(CI) do {                                           \
    const int k0_ = (CI) * 32;                                      \
    const uint32_t st_ = sb + ((CI) % 3) * IA_SZ;                   \
    const uint32_t d = st_ + crow * 80 + cu * 16;                   \
    const size_t ga = (size_t)(m0 + crow) * 256 + k0_ + cu * 8;     \
    const size_t gw = (size_t)crow * 256 + k0_ + cu * 8;            \
    CP_ASYNC16(d,         eh + ga);                                 \
    CP_ASYNC16(d + 5120,  el + ga);                                 \
    CP_ASYNC16(d + 10240, w1hp + gw);                               \
    CP_ASYNC16(d + 15360, w1lp + gw);                               \
    CP_COMMIT();                                                    \
} while (0)

        // ---- Phase A ----
        const int wmA = (w >> 1) * 16, wnA = (w & 1) * 32;
        float accA[4][4];
#pragma unroll
        for (int i = 0; i < 4; i++)
#pragma unroll
            for (int q = 0; q < 4; q++) accA[i][q] = 0.f;

        IN_ISSUE(0);
        IN_ISSUE(1);

#pragma unroll 1
        for (int ci = 0; ci < 8; ci++) {
            if (ci < 7) CP_WAIT1(); else CP_WAIT0();
            __syncthreads();
            if (ci < 6) IN_ISSUE(ci + 2);

            const uint32_t st = sb + (ci % 3) * IA_SZ;
#pragma unroll
            for (int kk = 0; kk < 32; kk += 16) {
                uint32_t ah[4], al[4];
                const uint32_t aaddr = st + (wmA + arow) * 80 + (kk + acol) * 2;
                LDSM4(ah, aaddr);
                LDSM4(al, aaddr + 5120);
                uint32_t bh[4][2], bl[4][2];
#pragma unroll
                for (int g = 0; g < 2; g++) {
                    const uint32_t baddr = st + 10240
                        + (wnA + g * 16 + brow) * 80 + (kk + bcol) * 2;
                    uint32_t r[4];
                    LDSM4(r, baddr);
                    bh[2 * g][0] = r[0]; bh[2 * g][1] = r[1];
                    bh[2 * g + 1][0] = r[2]; bh[2 * g + 1][1] = r[3];
                    LDSM4(r, baddr + 5120);
                    bl[2 * g][0] = r[0]; bl[2 * g][1] = r[1];
                    bl[2 * g + 1][0] = r[2]; bl[2 * g + 1][1] = r[3];
                }
#pragma unroll
                for (int nf = 0; nf < 4; nf++) {
                    mma_bf16(accA[nf], ah, bh[nf]);
                    mma_bf16(accA[nf], ah, bl[nf]);
                    mma_bf16(accA[nf], al, bh[nf]);
                }
            }
        }
#undef IN_ISSUE

        // Phase A epilogue: relu(+b1), split, store H to smem
        {
            const int r0 = wmA + (lane >> 2);
#pragma unroll
            for (int nf = 0; nf < 4; nf++) {
                const int col = wnA + nf * 8 + (lane & 3) * 2;
                const float bb0 = (col < HDIM)     ? b1[n * HDIM + col]     : 0.f;
                const float bb1 = (col + 1 < HDIM) ? b1[n * HDIM + col + 1] : 0.f;
                float v00 = fmaxf(accA[nf][0] + bb0, 0.f);
                float v01 = fmaxf(accA[nf][1] + bb1, 0.f);
                float v10 = fmaxf(accA[nf][2] + bb0, 0.f);
                float v11 = fmaxf(accA[nf][3] + bb1, 0.f);
                uint32_t h0, l0, h1, l1;
                split2(v00, v01, h0, l0);
                split2(v10, v11, h1, l1);
                *(uint32_t*)(smem + IN_HH + r0 * 144 + col * 2) = h0;
                *(uint32_t*)(smem + IN_HL + r0 * 144 + col * 2) = l0;
                *(uint32_t*)(smem + IN_HH + (r0 + 8) * 144 + col * 2) = h1;
                *(uint32_t*)(smem + IN_HL + (r0 + 8) * 144 + col * 2) = l1;
            }
        }
        __syncthreads();

        // ---- Phase B ----
#define IN_ISSUE_B(KK) do {                                         \
    const uint32_t st_ = sb + ((KK) % 3) * IB_SZ;                   \
    const uint32_t d = st_ + tid * 48;                              \
    const size_t g = (size_t)tid * 64 + (KK) * 16;                  \
    CP_ASYNC16(d,          wwhp + g);                               \
    CP_ASYNC16(d + 16,     wwhp + g + 8);                           \
    CP_ASYNC16(d + 12288,      wwlp + g);                           \
    CP_ASYNC16(d + 12288 + 16, wwlp + g + 8);                       \
    CP_COMMIT();                                                    \
} while (0)

        const int wmB = (w >> 1) * 16, wnB = (w & 1) * 128;
        float z[16][4];
#pragma unroll
        for (int nf = 0; nf < 16; nf++)
#pragma unroll
            for (int q = 0; q < 4; q++) z[nf][q] = 0.f;

        IN_ISSUE_B(0);
        IN_ISSUE_B(1);

#pragma unroll 1
        for (int kk = 0; kk < 4; kk++) {
            if (kk < 3) CP_WAIT1(); else CP_WAIT0();
            __syncthreads();
            if (kk < 2) IN_ISSUE_B(kk + 2);

            const uint32_t st = sb + (kk % 3) * IB_SZ;
            uint32_t ah[4], al[4];
            const uint32_t aaddr = sb + IN_HH + (wmB + arow) * 144 + (kk * 16 + acol) * 2;
            LDSM4(ah, aaddr);
            LDSM4(al, aaddr + (IN_HL - IN_HH));
#pragma unroll
            for (int g = 0; g < 8; g++) {
                const uint32_t baddr = st + (wnB + g * 16 + brow) * 48 + bcol * 2;
                uint32_t rh[4], rl[4];
                LDSM4(rh, baddr);
                LDSM4(rl, baddr + 12288);
                uint32_t b0h[2] = {rh[0], rh[1]}, b1h[2] = {rh[2], rh[3]};
                uint32_t b0l[2] = {rl[0], rl[1]}, b1l[2] = {rl[2], rl[3]};
                mma_bf16(z[2 * g],     ah, b0h);
                mma_bf16(z[2 * g],     ah, b0l);
                mma_bf16(z[2 * g],     al, b0h);
                mma_bf16(z[2 * g + 1], ah, b1h);
                mma_bf16(z[2 * g + 1], ah, b1l);
                mma_bf16(z[2 * g + 1], al, b1h);
            }
        }
#undef IN_ISSUE_B

        // ---- Phase B epilogue ----
        float* redmax = (float*)(smem + IN_RED);
        float* redse  = redmax + 128;
        float* redsx  = redse + 128;

        const int r0 = wmB + (lane >> 2), r1 = r0 + 8;
        float mx0 = -1e30f, mx1 = -1e30f;
#pragma unroll
        for (int nf = 0; nf < 16; nf++) {
            const int col = wnB + nf * 8 + (lane & 3) * 2;
            float2 bwv = *(const float2*)&bw[n * 256 + col];
            z[nf][0] += bwv.x; z[nf][1] += bwv.y;
            z[nf][2] += bwv.x; z[nf][3] += bwv.y;
            mx0 = fmaxf(mx0, fmaxf(z[nf][0], z[nf][1]));
            mx1 = fmaxf(mx1, fmaxf(z[nf][2], z[nf][3]));
        }
        mx0 = fmaxf(mx0, __shfl_xor_sync(0xffffffffu, mx0, 1));
        mx0 = fmaxf(mx0, __shfl_xor_sync(0xffffffffu, mx0, 2));
        mx1 = fmaxf(mx1, __shfl_xor_sync(0xffffffffu, mx1, 1));
        mx1 = fmaxf(mx1, __shfl_xor_sync(0xffffffffu, mx1, 2));
        if ((lane & 3) == 0) {
            redmax[(w & 1) * 64 + r0] = mx0;
            redmax[(w & 1) * 64 + r1] = mx1;
        }
        __syncthreads();
        mx0 = fmaxf(redmax[r0], redmax[64 + r0]);
        mx1 = fmaxf(redmax[r1], redmax[64 + r1]);

        float se0 = 0.f, sx0 = 0.f, se1 = 0.f, sx1 = 0.f;
        const float* x0 = x + (size_t)(m0 + r0) * 256;
        const float* x1 = x + (size_t)(m0 + r1) * 256;
#pragma unroll
        for (int nf = 0; nf < 16; nf++) {
            const int col = wnB + nf * 8 + (lane & 3) * 2;
            float2 xv0 = *(const float2*)&x0[col];
            float2 xv1 = *(const float2*)&x1[col];
            float e;
            e = __expf(z[nf][0] - mx0); se0 += e; sx0 = fmaf(e, xv0.x, sx0);
            e = __expf(z[nf][1] - mx0); se0 += e; sx0 = fmaf(e, xv0.y, sx0);
            e = __expf(z[nf][2] - mx1); se1 += e; sx1 = fmaf(e, xv1.x, sx1);
            e = __expf(z[nf][3] - mx1); se1 += e; sx1 = fmaf(e, xv1.y, sx1);
        }
#pragma unroll
        for (int off = 1; off <= 2; off <<= 1) {
            se0 += __shfl_xor_sync(0xffffffffu, se0, off);
            sx0 += __shfl_xor_sync(0xffffffffu, sx0, off);
            se1 += __shfl_xor_sync(0xffffffffu, se1, off);
            sx1 += __shfl_xor_sync(0xffffffffu, sx1, off);
        }
        if ((lane & 3) == 0) {
            redse[(w & 1) * 64 + r0] = se0; redse[(w & 1) * 64 + r1] = se1;
            redsx[(w & 1) * 64 + r0] = sx0; redsx[(w & 1) * 64 + r1] = sx1;
        }
        __syncthreads();

        if ((w & 1) == 0) {
            float pb0 = 0.f, pbt0 = 0.f, pb1 = 0.f, pbt1 = 0.f;
            for (int j = (lane & 3); j < HDIM; j += 4) {
                float h0 = __bfloat162float(*(const __nv_bfloat16*)(smem + IN_HH + r0 * 144 + j * 2))
                         + __bfloat162float(*(const __nv_bfloat16*)(smem + IN_HL + r0 * 144 + j * 2));
                float h1 = __bfloat162float(*(const __nv_bfloat16*)(smem + IN_HH + r1 * 144 + j * 2))
                         + __bfloat162float(*(const __nv_bfloat16*)(smem + IN_HL + r1 * 144 + j * 2));
                pb0  = fmaf(h0, sWb[j],  pb0);
                pbt0 = fmaf(h0, sWbt[j], pbt0);
                pb1  = fmaf(h1, sWb[j],  pb1);
                pbt1 = fmaf(h1, sWbt[j], pbt1);
            }
#pragma unroll
            for (int off = 1; off <= 2; off <<= 1) {
                pb0  += __shfl_xor_sync(0xffffffffu, pb0, off);
                pbt0 += __shfl_xor_sync(0xffffffffu, pbt0, off);
                pb1  += __shfl_xor_sync(0xffffffffu, pb1, off);
                pbt1 += __shfl_xor_sync(0xffffffffu, pbt1, off);
            }
            if ((lane & 3) == 0) {
                const float bbn = bb[n], bbtn = bbt[n];
                float seA = redse[r0] + redse[64 + r0];
                float sxA = redsx[r0] + redsx[64 + r0];
                float val = (pbt0 + bbtn) * (sxA / seA + pb0 + bbn);
                pR[(size_t)n * BATCH + m0 + r0] = 1.f / (1.f + __expf(-val));
                seA = redse[r1] + redse[64 + r1];
                sxA = redsx[r1] + redsx[64 + r1];
                val = (pbt1 + bbtn) * (sxA / seA + pb1 + bbn);
                pR[(size_t)n * BATCH + m0 + r1] = 1.f / (1.f + __expf(-val));
            }
        }
    } else {
        // ================= LEAF path =================
        const int mat = blockIdx.x - N_INNER;
        const int m0 = (blockIdx.y >> 1) * 128;
        const int n0 = (blockIdx.y & 1) * 128;
        const int wm = (w >> 1) * 32;
        const int wn = (w & 1) * 64;

        const __nv_bfloat16* bhp = Bh + (size_t)mat * 65536;
        const __nv_bfloat16* blp = Bl + (size_t)mat * 65536;

        float* s_bias = (float*)(smem + 2 * L_STAGE);
        float* s_w2   = (float*)(smem + 2 * L_STAGE + 512);
        if (tid < 128) {
            s_bias[tid] = lbias[(size_t)mat * 256 + n0 + tid];
            s_w2[tid]   = w2[(size_t)mat * 256 + n0 + tid];
        }

        float c[2][8][4];
#pragma unroll
        for (int mf = 0; mf < 2; mf++)
#pragma unroll
            for (int nf = 0; nf < 8; nf++)
#pragma unroll
                for (int q = 0; q < 4; q++) c[mf][nf][q] = 0.f;

#define L_ISSUE(CI) do {                                                        \
    const int k0_ = (CI) * 32;                                                  \
    const uint32_t st_ = sb + ((CI) & 1) * L_STAGE;                             \
    const uint32_t d0 = st_ + crow * 80 + cu * 16;                              \
    const uint32_t d1 = st_ + (crow + 64) * 80 + cu * 16;                       \
    const size_t ga = (size_t)(m0 + crow) * 256 + k0_ + cu * 8;                 \
    const size_t gb = (size_t)(n0 + crow) * 256 + k0_ + cu * 8;                 \
    CP_ASYNC16(d0,                  eh + ga);                                   \
    CP_ASYNC16(d1,                  eh + ga + 64 * 256);                        \
    CP_ASYNC16(d0 + L_TILE,         el + ga);                                   \
    CP_ASYNC16(d1 + L_TILE,         el + ga + 64 * 256);                        \
    CP_ASYNC16(d0 + 2 * L_TILE,     bhp + gb);                                  \
    CP_ASYNC16(d1 + 2 * L_TILE,     bhp + gb + 64 * 256);                       \
    CP_ASYNC16(d0 + 3 * L_TILE,     blp + gb);                                  \
    CP_ASYNC16(d1 + 3 * L_TILE,     blp + gb + 64 * 256);                       \
    CP_COMMIT();                                                                \
} while (0)

        L_ISSUE(0);

#pragma unroll 1
        for (int ci = 0; ci < 8; ci++) {
            if (ci < 7) { L_ISSUE(ci + 1); CP_WAIT1(); }
            else        { CP_WAIT0(); }
            __syncthreads();

            const uint32_t st = sb + (ci & 1) * L_STAGE;
#pragma unroll
            for (int kk = 0; kk < 32; kk += 16) {
                uint32_t ah[2][4], al[2][4];
#pragma unroll
                for (int mf = 0; mf < 2; mf++) {
                    uint32_t addr = st + (wm + mf * 16 + arow) * 80 + (kk + acol) * 2;
                    LDSM4(ah[mf], addr);
                    LDSM4(al[mf], addr + L_TILE);
                }
                uint32_t bhf[8][2], blf[8][2];
#pragma unroll
                for (int np = 0; np < 4; np++) {
                    uint32_t addr = st + 2 * L_TILE
                                  + (wn + np * 16 + brow) * 80 + (kk + bcol) * 2;
                    uint32_t r[4];
                    LDSM4(r, addr);
                    bhf[2 * np][0] = r[0]; bhf[2 * np][1] = r[1];
                    bhf[2 * np + 1][0] = r[2]; bhf[2 * np + 1][1] = r[3];
                    LDSM4(r, addr + L_TILE);
                    blf[2 * np][0] = r[0]; blf[2 * np][1] = r[1];
                    blf[2 * np + 1][0] = r[2]; blf[2 * np + 1][1] = r[3];
                }
#pragma unroll
                for (int mf = 0; mf < 2; mf++)
#pragma unroll
                    for (int nf = 0; nf < 8; nf++) {
                        mma_bf16(c[mf][nf], ah[mf], bhf[nf]);
                        mma_bf16(c[mf][nf], ah[mf], blf[nf]);
                        mma_bf16(c[mf][nf], al[mf], bhf[nf]);
                    }
            }
            __syncthreads();
        }
#undef L_ISSUE

        const int erow = lane >> 2;
        const int ecol = (lane & 3) * 2;
        float part[2][2] = {{0.f, 0.f}, {0.f, 0.f}};
#pragma unroll
        for (int mf = 0; mf < 2; mf++)
#pragma unroll
            for (int nf = 0; nf < 8; nf++) {
                const int lc = wn + nf * 8 + ecol;
                const float b0s = s_bias[lc], b1s = s_bias[lc + 1];
                const float w0 = s_w2[lc], w1 = s_w2[lc + 1];
                part[mf][0] = fmaf(fmaxf(c[mf][nf][0] + b0s, 0.f), w0, part[mf][0]);
                part[mf][0] = fmaf(fmaxf(c[mf][nf][1] + b1s, 0.f), w1, part[mf][0]);
                part[mf][1] = fmaf(fmaxf(c[mf][nf][2] + b0s, 0.f), w0, part[mf][1]);
                part[mf][1] = fmaf(fmaxf(c[mf][nf][3] + b1s, 0.f), w1, part[mf][1]);
            }
#pragma unroll
        for (int mf = 0; mf < 2; mf++)
#pragma unroll
            for (int h = 0; h < 2; h++) {
                part[mf][h] += __shfl_xor_sync(0xffffffffu, part[mf][h], 1);
                part[mf][h] += __shfl_xor_sync(0xffffffffu, part[mf][h], 2);
            }
        if ((lane & 3) == 0) {
#pragma unroll
            for (int mf = 0; mf < 2; mf++)
#pragma unroll
                for (int h = 0; h < 2; h++) {
                    const int row = m0 + wm + mf * 16 + h * 8 + erow;
                    atomicAdd(&yleaf[(size_t)mat * BATCH + row], part[mf][h]);
                }
        }
    }
}

// ---------------------------------------------------------------------------
// Combine
// ---------------------------------------------------------------------------
__global__ __launch_bounds__(256) void combine_kernel(
    const float* __restrict__ pR, const float* __restrict__ yl,
    const float* __restrict__ b2, float* __restrict__ out)
{
    const int b = blockIdx.x * 256 + threadIdx.x;
    float p[N_INNER];
#pragma unroll
    for (int i = 0; i < N_INNER; i++) p[i] = pR[(size_t)i * BATCH + b];

    float prob[N_LEAF];
    prob[0] = 1.f;
#pragma unroll
    for (int lev = 0; lev < 5; lev++) {
        const int cnt = 1 << lev;
        const int off = cnt - 1;
#pragma unroll
        for (int i = N_LEAF - 1; i >= 0; i--) {
            if (i < cnt) {
                float pr   = p[off + i];
                float base = prob[i];
                prob[2 * i]     = base * (1.f - pr);
                prob[2 * i + 1] = base * pr;
            }
        }
    }
    float acc = 0.f;
#pragma unroll
    for (int l = 0; l < N_LEAF; l++)
        acc = fmaf(prob[l], yl[(size_t)l * BATCH + b] + b2[l], acc);
    out[b] = acc;
}

// ---------------------------------------------------------------------------
extern "C" void kernel_launch(void* const* d_in, const int* in_sizes, int n_in,
                              void* d_out, int out_size)
{
    const float* x       = (const float*)d_in[0];
    const float* enc_W   = (const float*)d_in[1];
    const float* enc_b   = (const float*)d_in[2];
    const float* in_W1   = (const float*)d_in[3];
    const float* in_b1   = (const float*)d_in[4];
    const float* in_Ww   = (const float*)d_in[5];
    const float* in_bw   = (const float*)d_in[6];
    const float* in_Wb   = (const float*)d_in[7];
    const float* in_bb   = (const float*)d_in[8];
    const float* in_Wbt  = (const float*)d_in[9];
    const float* in_bbt  = (const float*)d_in[10];
    const float* lf_W1   = (const float*)d_in[11];
    const float* lf_b1   = (const float*)d_in[12];
    const float* lf_W2   = (const float*)d_in[13];
    const float* lf_b2   = (const float*)d_in[14];
    float* out = (float*)d_out;

    float *pR, *yl;
    __nv_bfloat16 *xh, *xl, *e0h, *e0l, *e1h, *e1l, *wth, *wtl;
    __nv_bfloat16 *w1th, *w1tl, *wwth, *wwtl;
    cudaGetSymbolAddress((void**)&pR,  g_pR);
    cudaGetSymbolAddress((void**)&yl,  g_yleaf);
    cudaGetSymbolAddress((void**)&xh,  g_xh);
    cudaGetSymbolAddress((void**)&xl,  g_xl);
    cudaGetSymbolAddress((void**)&e0h, g_e0h);
    cudaGetSymbolAddress((void**)&e0l, g_e0l);
    cudaGetSymbolAddress((void**)&e1h, g_e1h);
    cudaGetSymbolAddress((void**)&e1l, g_e1l);
    cudaGetSymbolAddress((void**)&wth, g_wth);
    cudaGetSymbolAddress((void**)&wtl, g_wtl);
    cudaGetSymbolAddress((void**)&w1th, g_w1th);
    cudaGetSymbolAddress((void**)&w1tl, g_w1tl);
    cudaGetSymbolAddress((void**)&wwth, g_wwth);
    cudaGetSymbolAddress((void**)&wwtl, g_wwtl);

    cudaFuncSetAttribute(enc_kernel,  cudaFuncAttributeMaxDynamicSharedMemorySize, ENC_SMEM);
    cudaFuncSetAttribute(tail_kernel, cudaFuncAttributeMaxDynamicSharedMemorySize, TAIL_SMEM);

    // 1) all prep in one launch
    prep_all_kernel<<<PR_WT, 256>>>(x, xh, xl, in_W1, w1th, w1tl,
                                    in_Ww, wwth, wwtl, yl,
                                    enc_W, lf_W1, wth, wtl);

    // 2-5) encoder
    enc_kernel<<<dim3(128, 2), 256, ENC_SMEM>>>(xh, xl, wth, wtl,
        enc_b, e0h, e0l);
    enc_kernel<<<dim3(128, 2), 256, ENC_SMEM>>>(e0h, e0l, wth + 65536, wtl + 65536,
        enc_b + 256, e1h, e1l);
    enc_kernel<<<dim3(128, 2), 256, ENC_SMEM>>>(e1h, e1l, wth + 2 * 65536, wtl + 2 * 65536,
        enc_b + 512, e0h, e0l);
    enc_kernel<<<dim3(128, 2), 256, ENC_SMEM>>>(e0h, e0l, wth + 3 * 65536, wtl + 3 * 65536,
        enc_b + 768, e1h, e1l);

    // 6) merged inner + leaf (profiled launch)
    tail_kernel<<<dim3(63, 128), 256, TAIL_SMEM>>>(
        e1h, e1l,
        w1th, w1tl, wwth, wwtl, x, in_b1, in_bw, in_Wb, in_bb, in_Wbt, in_bbt, pR,
        wth + 4 * 65536, wtl + 4 * 65536, lf_b1, lf_W2, yl);

    // 7) combine
    combine_kernel<<<BATCH / 256, 256>>>(pR, yl, lf_b2, out);
}